// round 15
// baseline (speedup 1.0000x reference)
#include <cuda_runtime.h>
#include <math.h>

#define NN 4096
#define C1 256
#define C2 512
#define CHW (256*4096)
#define CRP 256   // colred_part blocks

// ---------------- static scratch (no allocations allowed) ----------------
__device__ float g_xr[2*CHW];
__device__ float g_pos[CHW];
__device__ float g_bnsc[C1], g_bnsh[C1];
__device__ float g_partS[CRP*C2], g_partQ[CRP*C2];
__device__ float g_invn_s[C1], g_invn2_s[C1];
__device__ float g_invn_q[C1], g_invn2_q[C1];
__device__ float g_invn_e1[C2], g_dummy1[C2];
__device__ float g_invn_e2[C2], g_dummy2[C2];
__device__ float g_invee[C2];
__device__ float g_fsc[C2], g_fsh[C2];
__device__ float g_colabsPart[32*NN];
__device__ float g_invcol_s[NN], g_invcol_q[NN];
__device__ unsigned int g_rmax_ord;
__device__ float g_inv_rmax;
__device__ float g_ax[NN*C2];
__device__ float g_ux[NN*C2];
__device__ float g_Tt[C2*C2];
__device__ float g_Tpart[16*C2*C2];
__device__ float g_emb1[NN*C2];
__device__ float g_emb2[NN*C2];
__device__ float g_r2[NN*C2];
__device__ float g_y2[NN*C2];

__device__ __forceinline__ unsigned ord_of_float(float f) {
    unsigned u = __float_as_uint(f);
    return (u & 0x80000000u) ? ~u : (u | 0x80000000u);
}
__device__ __forceinline__ unsigned f2tf32(float v) {
    unsigned r; asm("cvt.rna.tf32.f32 %0, %1;" : "=r"(r) : "f"(v)); return r;
}
__device__ __forceinline__ void mma_tf32(float* d, const unsigned* a, const unsigned* b) {
    asm volatile("mma.sync.aligned.m16n8k8.row.col.f32.tf32.tf32.f32 "
        "{%0,%1,%2,%3}, {%4,%5,%6,%7}, {%8,%9}, {%0,%1,%2,%3};"
        : "+f"(d[0]), "+f"(d[1]), "+f"(d[2]), "+f"(d[3])
        : "r"(a[0]), "r"(a[1]), "r"(a[2]), "r"(a[3]), "r"(b[0]), "r"(b[1]));
}

// ---------------- generic SGEMM 128x128x16, double-buffered smem ----------------
// (kept for conv1 / split-K partials — layouts hostile to the tf32 path)
template<int TA, int TB>
__global__ void __launch_bounds__(256)
gemm_k(int M, int N, int K,
       const float* __restrict__ A, int lda, size_t sA,
       const float* __restrict__ B, int ldb, size_t sB,
       float* __restrict__ C, size_t sC,
       const float* __restrict__ ksA, const float* __restrict__ ksB,
       int splitLen, float alphaS, const float* __restrict__ alphaPtr,
       const float* __restrict__ bias,
       const float* __restrict__ addMat, int doRelu)
{
    __shared__ float As[2][16][128];
    __shared__ float Bs[2][16][128];
    const int tid = threadIdx.x;
    const int tx = tid & 15, ty = tid >> 4;
    const int n0 = blockIdx.x * 128;
    const int m0 = blockIdx.y * 128;
    const int z  = blockIdx.z;

    int k0, kEnd;
    if (splitLen > 0) { k0 = z * splitLen; kEnd = k0 + splitLen; C += (size_t)z * M * N; }
    else { k0 = 0; kEnd = K; A += (size_t)z*sA; B += (size_t)z*sB; C += (size_t)z*sC; }

    float acc[8][8];
    #pragma unroll
    for (int i=0;i<8;i++)
        #pragma unroll
        for (int j=0;j<8;j++) acc[i][j]=0.f;

    float4 rA0, rA1, rB0, rB1;

    auto loadA = [&](int kk, float4& a0, float4& a1) {
        if (TA == 0) {
            int m = tid >> 1, k8 = (tid & 1) * 8;
            const float* src = A + (size_t)(m0+m)*lda + kk + k8;
            a0 = *(const float4*)src; a1 = *(const float4*)(src+4);
        } else {
            int k = tid >> 4, m8 = (tid & 15) * 8;
            const float* src = A + (size_t)(kk+k)*lda + m0 + m8;
            a0 = *(const float4*)src; a1 = *(const float4*)(src+4);
        }
    };
    auto loadB = [&](int kk, float4& b0, float4& b1) {
        if (TB == 0) {
            int k = tid >> 4, n8 = (tid & 15) * 8;
            const float* src = B + (size_t)(kk+k)*ldb + n0 + n8;
            b0 = *(const float4*)src; b1 = *(const float4*)(src+4);
        } else {
            int n = tid >> 1, k8 = (tid & 1) * 8;
            const float* src = B + (size_t)(n0+n)*ldb + kk + k8;
            b0 = *(const float4*)src; b1 = *(const float4*)(src+4);
        }
    };
    auto storeA = [&](int buf, int kk, const float4& a0, const float4& a1) {
        float vv[8] = {a0.x,a0.y,a0.z,a0.w,a1.x,a1.y,a1.z,a1.w};
        if (TA == 0) {
            int m = tid >> 1, k8 = (tid & 1) * 8;
            #pragma unroll
            for (int i=0;i<8;i++) {
                float s = ksA ? ksA[kk+k8+i] : 1.f;
                As[buf][k8+i][m] = vv[i]*s;
            }
        } else {
            int k = tid >> 4, m8 = (tid & 15) * 8;
            float s = ksA ? ksA[kk+k] : 1.f;
            #pragma unroll
            for (int i=0;i<8;i++) As[buf][k][m8+i] = vv[i]*s;
        }
    };
    auto storeB = [&](int buf, int kk, const float4& b0, const float4& b1) {
        float vv[8] = {b0.x,b0.y,b0.z,b0.w,b1.x,b1.y,b1.z,b1.w};
        if (TB == 0) {
            int k = tid >> 4, n8 = (tid & 15) * 8;
            float s = ksB ? ksB[kk+k] : 1.f;
            #pragma unroll
            for (int i=0;i<8;i++) Bs[buf][k][n8+i] = vv[i]*s;
        } else {
            int n = tid >> 1, k8 = (tid & 1) * 8;
            #pragma unroll
            for (int i=0;i<8;i++) {
                float s = ksB ? ksB[kk+k8+i] : 1.f;
                Bs[buf][k8+i][n] = vv[i]*s;
            }
        }
    };

    loadA(k0, rA0, rA1); loadB(k0, rB0, rB1);
    storeA(0, k0, rA0, rA1); storeB(0, k0, rB0, rB1);
    __syncthreads();

    int buf = 0;
    for (int kk = k0; kk < kEnd; kk += 16) {
        const bool hasNext = (kk + 16) < kEnd;
        if (hasNext) { loadA(kk+16, rA0, rA1); loadB(kk+16, rB0, rB1); }
        #pragma unroll
        for (int k=0;k<16;k++) {
            float4 a0 = *(const float4*)&As[buf][k][ty*4];
            float4 a1 = *(const float4*)&As[buf][k][ty*4+64];
            float4 b0 = *(const float4*)&Bs[buf][k][tx*4];
            float4 b1 = *(const float4*)&Bs[buf][k][tx*4+64];
            float a[8] = {a0.x,a0.y,a0.z,a0.w,a1.x,a1.y,a1.z,a1.w};
            float b[8] = {b0.x,b0.y,b0.z,b0.w,b1.x,b1.y,b1.z,b1.w};
            #pragma unroll
            for (int i=0;i<8;i++)
                #pragma unroll
                for (int j=0;j<8;j++)
                    acc[i][j] += a[i]*b[j];
        }
        if (hasNext) {
            storeA(buf^1, kk+16, rA0, rA1);
            storeB(buf^1, kk+16, rB0, rB1);
            __syncthreads();
            buf ^= 1;
        }
    }

    if (splitLen > 0) {
        #pragma unroll
        for (int i=0;i<8;i++) {
            int m = m0 + ty*4 + (i&3) + ((i>>2)<<6);
            #pragma unroll
            for (int j=0;j<8;j++) {
                int n = n0 + tx*4 + (j&3) + ((j>>2)<<6);
                C[(size_t)m*N + n] = acc[i][j];
            }
        }
        return;
    }
    float alpha = alphaS * (alphaPtr ? *alphaPtr : 1.f);
    #pragma unroll
    for (int i=0;i<8;i++) {
        int m = m0 + ty*4 + (i&3) + ((i>>2)<<6);
        #pragma unroll
        for (int j=0;j<8;j++) {
            int n = n0 + tx*4 + (j&3) + ((j>>2)<<6);
            float v = acc[i][j]*alpha;
            if (bias)   v += bias[n];
            if (addMat) v += addMat[(size_t)m*N + n];
            if (doRelu) v = fmaxf(v, 0.f);
            C[(size_t)m*N + n] = v;
        }
    }
}

// --- tf32x3 tensor GEMM: C = act( alpha*(A*ksA)@B^T + bias + addMat ) ---
// A (M,K) rm, B (N,K) rm. Block 128x128, 256 thr, 8 warps (2m x 4n),
// warp 64x32 (proven R13 shape). Smem holds FP32 (exact); the hi/lo tf32
// split happens in registers after the fragment load -> ~0.55x L1 bytes.
// k-tile 8. Optional A2/Ksplit: fused concat-K. gridDim.z==2 batching.
__global__ void __launch_bounds__(256)
gemm_t32(int M, int N, int K,
         const float* __restrict__ A, int lda,
         const float* __restrict__ A2, int Ksplit,
         const float* __restrict__ B, int ldb,
         float* __restrict__ C,
         const float* __restrict__ ksA,
         float alphaS, const float* __restrict__ alphaPtr,
         const float* __restrict__ bias,
         const float* __restrict__ addMat, int doRelu,
         const float* __restrict__ Bz, const float* __restrict__ biasz,
         float* __restrict__ Cz)
{
    // 16KB fp32: A [2][1024] @0, B [2][1024] @2048
    __shared__ float shf[4096];
    const int tid = threadIdx.x, lane = tid & 31, wid = tid >> 5;
    const int wm = wid >> 2, wn = wid & 3;
    const int n0 = blockIdx.x * 128, m0 = blockIdx.y * 128;
    const int r = lane >> 2, c = lane & 3;
    const bool isA = tid < 128;
    const int row = isA ? tid : tid - 128;

    if (blockIdx.z == 1) { B = Bz; bias = biasz; C = Cz; }

    float acc[4][4][4];
    #pragma unroll
    for (int mf=0; mf<4; mf++)
        #pragma unroll
        for (int nf=0; nf<4; nf++)
            #pragma unroll
            for (int q=0; q<4; q++) acc[mf][nf][q] = 0.f;

    float4 v0, v1;
    auto ldg = [&](int kk) {
        const float* p;
        if (isA) {
            const float* base = A; int kx = kk;
            if (A2 && kk >= Ksplit) { base = A2; kx = kk - Ksplit; }
            p = base + (size_t)(m0+row)*lda + kx;
        } else {
            p = B + (size_t)(n0+row)*ldb + kk;
        }
        v0 = *(const float4*)p; v1 = *(const float4*)(p+4);
    };
    // permuted-k store {0,4,1,5,2,6,3,7}: fragment pair (k=c, k=c+4) is one LDS.64
    auto sts = [&](int buf, int kk) {
        float a[8] = {v0.x,v0.y,v0.z,v0.w,v1.x,v1.y,v1.z,v1.w};
        if (isA && ksA) {
            #pragma unroll
            for (int i=0;i<8;i++) a[i] *= ksA[kk+i];
        }
        float* p = &shf[(isA ? 0 : 2048) + buf*1024 + row*8];
        *(float4*)p     = make_float4(a[0],a[4],a[1],a[5]);
        *(float4*)(p+4) = make_float4(a[2],a[6],a[3],a[7]);
    };

    ldg(0); sts(0, 0);
    __syncthreads();

    int buf = 0;
    for (int kk = 0; kk < K; kk += 8) {
        const bool nxt = (kk + 8) < K;
        if (nxt) ldg(kk + 8);
        const float* Af = &shf[buf*1024];
        const float* Bf = &shf[2048 + buf*1024];
        unsigned afh[4][4], afl[4][4], bfh[4][2], bfl[4][2];
        #pragma unroll
        for (int mf=0; mf<4; mf++) {
            int m = wm*64 + mf*16;
            float2 p = *(const float2*)&Af[(m+r)*8 + 2*c];
            float2 q = *(const float2*)&Af[(m+r+8)*8 + 2*c];
            float av[4] = {p.x, q.x, p.y, q.y};
            #pragma unroll
            for (int i=0;i<4;i++) {
                afh[mf][i] = f2tf32(av[i]);
                afl[mf][i] = f2tf32(av[i] - __uint_as_float(afh[mf][i]));
            }
        }
        #pragma unroll
        for (int nf=0; nf<4; nf++) {
            float2 p = *(const float2*)&Bf[(wn*32 + nf*8 + r)*8 + 2*c];
            bfh[nf][0] = f2tf32(p.x);
            bfl[nf][0] = f2tf32(p.x - __uint_as_float(bfh[nf][0]));
            bfh[nf][1] = f2tf32(p.y);
            bfl[nf][1] = f2tf32(p.y - __uint_as_float(bfh[nf][1]));
        }
        #pragma unroll
        for (int mf=0; mf<4; mf++)
            #pragma unroll
            for (int nf=0; nf<4; nf++) {
                mma_tf32(acc[mf][nf], afl[mf], bfh[nf]);
                mma_tf32(acc[mf][nf], afh[mf], bfl[nf]);
                mma_tf32(acc[mf][nf], afh[mf], bfh[nf]);
            }
        if (nxt) {
            sts(buf^1, kk + 8);
            __syncthreads();
            buf ^= 1;
        }
    }

    // acc[mf][nf][q]: row = m0+wm*64+mf*16+r+(q>=2?8:0), col = n0+wn*32+nf*8+2c+(q&1)
    float alpha = alphaS * (alphaPtr ? *alphaPtr : 1.f);
    #pragma unroll
    for (int mf=0; mf<4; mf++) {
        #pragma unroll
        for (int h=0; h<2; h++) {
            int orow = m0 + wm*64 + mf*16 + r + h*8;
            #pragma unroll
            for (int nf=0; nf<4; nf++) {
                int col = n0 + wn*32 + nf*8 + 2*c;
                float w0 = acc[mf][nf][h*2]   * alpha;
                float w1 = acc[mf][nf][h*2+1] * alpha;
                if (bias)   { w0 += bias[col]; w1 += bias[col+1]; }
                if (addMat) { w0 += addMat[(size_t)orow*N + col];
                              w1 += addMat[(size_t)orow*N + col + 1]; }
                if (doRelu) { w0 = fmaxf(w0, 0.f); w1 = fmaxf(w1, 0.f); }
                *(float2*)&C[(size_t)orow*N + col] = make_float2(w0, w1);
            }
        }
    }
}

// ---- split-K reduce with fused transpose: out[n*M+m] = sum_z part[z][m][n] ----
// 32x32 tiles for parallelism (grid = (M/32, N/32)).
__global__ void splitk_reduceT(int S, int M, int N,
                               const float* __restrict__ part,
                               float* __restrict__ out)
{
    __shared__ float t[32][33];
    int m0 = blockIdx.x*32, n0 = blockIdx.y*32;
    int g = threadIdx.x >> 5, ln = threadIdx.x & 31;
    #pragma unroll
    for (int i=0;i<4;i++) {
        int m = g*4 + i;
        float s = 0.f;
        #pragma unroll 4
        for (int z=0;z<16;z++)
            s += part[((size_t)z*M + m0+m)*N + n0+ln];
        t[m][ln] = s;
    }
    __syncthreads();
    #pragma unroll
    for (int i=0;i<4;i++) {
        int n = g*4 + i;
        out[(size_t)(n0+n)*M + m0 + ln] = t[ln][n];
    }
}

// ------------- streamed Gram stats via tf32 mma: G = (A*scA)(B*scB)^T ---------
__global__ void __launch_bounds__(256)
gram_tf32(int Cc,
          const float* __restrict__ A, int lda, const float* __restrict__ scA,
          const float* __restrict__ Bm, int ldb, const float* __restrict__ scB,
          float* __restrict__ colAbsPart, unsigned int* __restrict__ maxOrd)
{
    __shared__ unsigned sh[12288];   // exactly 48KB
    const int tid = threadIdx.x, lane = tid & 31, wid = tid >> 5;
    const int wm = wid >> 2, wn = wid & 3;
    const int m0 = blockIdx.x * 256;   // cols (Bm rows)
    const int n0 = blockIdx.y * 128;   // rows (A rows)
    const int r = lane >> 2, c = lane & 3;
    const int ar = tid >> 1, asl = tid & 1;

    float acc[4][8][4];
    #pragma unroll
    for (int mf=0; mf<4; mf++)
        #pragma unroll
        for (int nf=0; nf<8; nf++)
            #pragma unroll
            for (int q=0; q<4; q++) acc[mf][nf][q] = 0.f;

    float4 vA0, vA1, vB0, vB1, vB2, vB3;
    auto ldg = [&](int cc) {
        const float* pa = A + (size_t)(n0+ar)*lda + cc + asl*8;
        vA0 = *(const float4*)pa; vA1 = *(const float4*)(pa+4);
        const float* pb = Bm + (size_t)(m0+tid)*ldb + cc;
        vB0 = *(const float4*)pb;     vB1 = *(const float4*)(pb+4);
        vB2 = *(const float4*)(pb+8); vB3 = *(const float4*)(pb+12);
    };
    auto sts = [&](int buf, int cc) {
        float a[8] = {vA0.x,vA0.y,vA0.z,vA0.w,vA1.x,vA1.y,vA1.z,vA1.w};
        #pragma unroll
        for (int i=0;i<8;i++) a[i] *= scA[cc + asl*8 + i];
        uint4 u0 = make_uint4(f2tf32(a[0]), f2tf32(a[4]), f2tf32(a[1]), f2tf32(a[5]));
        uint4 u1 = make_uint4(f2tf32(a[2]), f2tf32(a[6]), f2tf32(a[3]), f2tf32(a[7]));
        unsigned* ab = &sh[buf*2048 + asl*1024 + ar*8];
        *(uint4*)ab = u0; *(uint4*)(ab+4) = u1;
        float b[16] = {vB0.x,vB0.y,vB0.z,vB0.w, vB1.x,vB1.y,vB1.z,vB1.w,
                       vB2.x,vB2.y,vB2.z,vB2.w, vB3.x,vB3.y,vB3.z,vB3.w};
        #pragma unroll
        for (int i=0;i<16;i++) b[i] *= scB[cc + i];
        uint4 w0 = make_uint4(f2tf32(b[0]),  f2tf32(b[4]),  f2tf32(b[1]),  f2tf32(b[5]));
        uint4 w1 = make_uint4(f2tf32(b[2]),  f2tf32(b[6]),  f2tf32(b[3]),  f2tf32(b[7]));
        uint4 w2 = make_uint4(f2tf32(b[8]),  f2tf32(b[12]), f2tf32(b[9]),  f2tf32(b[13]));
        uint4 w3 = make_uint4(f2tf32(b[10]), f2tf32(b[14]), f2tf32(b[11]), f2tf32(b[15]));
        unsigned* bb = &sh[4096 + buf*4096 + tid*8];
        *(uint4*)bb = w0; *(uint4*)(bb+4) = w1;
        *(uint4*)(bb+2048) = w2; *(uint4*)(bb+2048+4) = w3;
    };

    ldg(0); sts(0, 0);
    __syncthreads();

    int buf = 0;
    for (int cc = 0; cc < Cc; cc += 16) {
        const bool nxt = (cc + 16) < Cc;
        if (nxt) ldg(cc + 16);
        #pragma unroll
        for (int s=0; s<2; s++) {
            const unsigned* Ab = &sh[buf*2048 + s*1024];
            const unsigned* Bb = &sh[4096 + buf*4096 + s*2048];
            unsigned af[4][4];
            #pragma unroll
            for (int mf=0; mf<4; mf++) {
                int m = wm*64 + mf*16;
                uint2 p = *(const uint2*)&Ab[(m+r)*8 + 2*c];
                uint2 q = *(const uint2*)&Ab[(m+r+8)*8 + 2*c];
                af[mf][0] = p.x; af[mf][1] = q.x; af[mf][2] = p.y; af[mf][3] = q.y;
            }
            unsigned bf[8][2];
            #pragma unroll
            for (int nf=0; nf<8; nf++) {
                uint2 p = *(const uint2*)&Bb[(wn*64 + nf*8 + r)*8 + 2*c];
                bf[nf][0] = p.x; bf[nf][1] = p.y;
            }
            #pragma unroll
            for (int mf=0; mf<4; mf++)
                #pragma unroll
                for (int nf=0; nf<8; nf++)
                    mma_tf32(acc[mf][nf], af[mf], bf[nf]);
        }
        if (nxt) {
            sts(buf^1, cc + 16);
            __syncthreads();
            buf ^= 1;
        }
    }
    float* cw  = (float*)&sh[4096];          // [8][64]
    float* wmx = (float*)&sh[4096 + 512];    // [8]

    if (colAbsPart) {
        #pragma unroll
        for (int nf=0; nf<8; nf++) {
            float s0 = 0.f, s1 = 0.f;
            #pragma unroll
            for (int mf=0; mf<4; mf++) {
                s0 += fabsf(acc[mf][nf][0]) + fabsf(acc[mf][nf][2]);
                s1 += fabsf(acc[mf][nf][1]) + fabsf(acc[mf][nf][3]);
            }
            #pragma unroll
            for (int off=4; off<32; off<<=1) {
                s0 += __shfl_xor_sync(0xffffffffu, s0, off);
                s1 += __shfl_xor_sync(0xffffffffu, s1, off);
            }
            if (lane < 4) {
                cw[wid*64 + nf*8 + 2*lane    ] = s0;
                cw[wid*64 + nf*8 + 2*lane + 1] = s1;
            }
        }
        __syncthreads();
        {
            int wn2 = tid >> 6, j = tid & 63;
            float s = cw[wn2*64 + j] + cw[(4+wn2)*64 + j];
            colAbsPart[(size_t)blockIdx.y*NN + m0 + tid] = s;
        }
    }
    if (maxOrd) {
        float mx = -3.4e38f;
        #pragma unroll
        for (int mf=0; mf<4; mf++)
            #pragma unroll
            for (int nf=0; nf<8; nf++)
                #pragma unroll
                for (int q=0; q<4; q++) mx = fmaxf(mx, acc[mf][nf][q]);
        #pragma unroll
        for (int off=16; off; off>>=1)
            mx = fmaxf(mx, __shfl_xor_sync(0xffffffffu, mx, off));
        if (lane == 0) wmx[wid] = mx;
        __syncthreads();
        if (tid == 0) {
            float m2 = wmx[0];
            #pragma unroll
            for (int t=1;t<8;t++) m2 = fmaxf(m2, wmx[t]);
            atomicMax(maxOrd, ord_of_float(m2));
        }
    }
}

// ---------------- small kernels ----------------
__global__ void convbn_stats(const float* __restrict__ xr, const float* __restrict__ g,
                             const float* __restrict__ b, float* sc, float* sh)
{
    int o = blockIdx.x;
    const float* p0 = xr + (size_t)o*4096;
    const float* p1 = xr + (size_t)CHW + (size_t)o*4096;
    float s=0.f, q=0.f;
    for (int i = threadIdx.x; i < 4096; i += 256) {
        float v = p0[i]; s += v; q += v*v;
        v = p1[i];       s += v; q += v*v;
    }
    __shared__ float ss[256], sq[256];
    ss[threadIdx.x]=s; sq[threadIdx.x]=q; __syncthreads();
    for (int off=128; off; off>>=1) {
        if (threadIdx.x < off) { ss[threadIdx.x]+=ss[threadIdx.x+off]; sq[threadIdx.x]+=sq[threadIdx.x+off]; }
        __syncthreads();
    }
    if (threadIdx.x == 0) {
        float mean = ss[0]/8192.f;
        float var  = sq[0]/8192.f - mean*mean;
        float scl  = g[o]*rsqrtf(var + 1e-5f);
        sc[o] = scl; sh[o] = b[o] - mean*scl;
    }
}

__global__ void bnrelu_k(float* x, const float* sc, const float* sh) {
    int i = blockIdx.x*256 + threadIdx.x;
    int o = (i >> 12) & 255;
    x[i] = fmaxf(x[i]*sc[o] + sh[o], 0.f);
}

__global__ void pos_kernel(const float* __restrict__ x0, const float* __restrict__ mask,
                           float* __restrict__ out)
{
    int gid = blockIdx.x*256 + threadIdx.x;
    int c = gid >> 12, p = gid & 4095;
    int i = p >> 6, j = p & 63;
    const float* img = x0 + (size_t)c*4096;
    float yd = i * (511.f/63.f);
    int Y0 = min((int)yd, 511), Y1 = min(Y0+1, 511);
    float wy = yd - (float)Y0;
    float xd = j * (511.f/63.f);
    int X0 = min((int)xd, 511), X1 = min(X0+1, 511);
    float wx = xd - (float)X0;
    int Ys[2]={Y0,Y1}; float wys[2]={1.f-wy, wy};
    int Xs[2]={X0,X1}; float wxs[2]={1.f-wx, wx};
    float acc = 0.f;
    #pragma unroll
    for (int a=0;a<2;a++) {
        int Y = Ys[a];
        float yu = Y*(63.f/511.f);
        int a0 = min((int)yu, 63), a1 = min(a0+1, 63);
        float wa = yu - (float)a0;
        #pragma unroll
        for (int b=0;b<2;b++) {
            int X = Xs[b];
            float xu = X*(63.f/511.f);
            int b0 = min((int)xu, 63), b1 = min(b0+1, 63);
            float wb = xu - (float)b0;
            float v = (img[a0*64+b0]*(1.f-wb) + img[a0*64+b1]*wb)*(1.f-wa)
                    + (img[a1*64+b0]*(1.f-wb) + img[a1*64+b1]*wb)*wa;
            acc += wys[a]*wxs[b]*mask[Y*512+X]*v;
        }
    }
    out[gid] = acc;
}

__global__ void colred_part(const float* __restrict__ X, int ld, int C,
                            float* __restrict__ pS, float* __restrict__ pQ)
{
    int r0 = blockIdx.x * (NN/CRP);
    int c0 = threadIdx.x, c1 = threadIdx.x + 256;
    float s0=0,q0=0,s1=0,q1=0;
    #pragma unroll 4
    for (int r=0;r<NN/CRP;r++) {
        const float* row = X + (size_t)(r0+r)*ld;
        float v = row[c0]; s0 += v; q0 += v*v;
        if (C > 256) { float w = row[c1]; s1 += w; q1 += w*w; }
    }
    pS[blockIdx.x*C + c0] = s0; pQ[blockIdx.x*C + c0] = q0;
    if (C > 256) { pS[blockIdx.x*C + c1] = s1; pQ[blockIdx.x*C + c1] = q1; }
}

// mode 0: o1=1/max(||col||,eps), o2=o1^2, optional o3=o1*mulv.
// mode 1: BN scale/shift over 4096 rows.
__global__ void colred_fin(const float* __restrict__ pS, const float* __restrict__ pQ,
                           int C, int mode,
                           const float* g, const float* b,
                           const float* mulv, float* o1, float* o2, float* o3)
{
    int c = blockIdx.x*256 + threadIdx.x;
    if (c >= C) return;
    float S=0.f, Q=0.f;
    #pragma unroll 4
    for (int z=0; z<CRP; z++) { S += pS[z*C+c]; Q += pQ[z*C+c]; }
    if (mode == 0) {
        float inv = 1.f / fmaxf(sqrtf(Q), 1e-12f);
        o1[c] = inv; o2[c] = inv*inv;
        if (mulv) o3[c] = inv * mulv[c];
    } else {
        float mean = S*(1.f/4096.f);
        float var  = Q*(1.f/4096.f) - mean*mean;
        float sc   = g[c]*rsqrtf(var + 1e-5f);
        o1[c] = sc; o2[c] = b[c] - mean*sc;
    }
}

__global__ void colabs_fin(const float* __restrict__ part, float* __restrict__ inv) {
    int m = blockIdx.x*256 + threadIdx.x;
    float s = 0.f;
    #pragma unroll 4
    for (int z=0; z<32; z++) s += part[z*NN + m];
    inv[m] = 1.f / fmaxf(s, 1e-12f);
}

__global__ void init_rmax_k(unsigned int* p) { *p = 0u; }
__global__ void fin_rmax_k(const unsigned int* p, float* o) {
    unsigned u = *p;
    unsigned f = (u & 0x80000000u) ? (u & 0x7fffffffu) : ~u;
    *o = 1.f / __uint_as_float(f);
}

__global__ void bnapply_k(const float* y, const float* sc, const float* sh, float* o) {
    int i = blockIdx.x*256 + threadIdx.x;
    int c = i & 511;
    o[i] = fmaxf(y[i]*sc[c] + sh[c], 0.f);
}

// ---------------- host ----------------
#define SYMF(name, sym) float* name; { void* _p=nullptr; cudaGetSymbolAddress(&_p, sym); name=(float*)_p; }

extern "C" void kernel_launch(void* const* d_in, const int* in_sizes, int n_in,
                              void* d_out, int out_size)
{
    const float* x      = (const float*)d_in[0];
    const float* mask   = (const float*)d_in[1];
    const float* conv1w = (const float*)d_in[2];
    const float* bn1g   = (const float*)d_in[3];
    const float* bn1b   = (const float*)d_in[4];
    const float* g0aw   = (const float*)d_in[5];
    const float* g0ab   = (const float*)d_in[6];
    const float* g0uw   = (const float*)d_in[7];
    const float* g0ub   = (const float*)d_in[8];
    const float* g1aw   = (const float*)d_in[9];
    const float* g1ab   = (const float*)d_in[10];
    const float* g1uw   = (const float*)d_in[11];
    const float* g1ub   = (const float*)d_in[12];
    const float* cgw    = (const float*)d_in[13];
    const float* cgb    = (const float*)d_in[14];
    const float* cgbng  = (const float*)d_in[15];
    const float* cgbnb  = (const float*)d_in[16];
    float* out = (float*)d_out;

    SYMF(xr, g_xr)       SYMF(pos, g_pos)
    SYMF(bnsc, g_bnsc)   SYMF(bnsh, g_bnsh)
    SYMF(pS, g_partS)    SYMF(pQ, g_partQ)
    SYMF(invn_s, g_invn_s)   SYMF(invn2_s, g_invn2_s)
    SYMF(invn_q, g_invn_q)   SYMF(invn2_q, g_invn2_q)
    SYMF(invn_e1, g_invn_e1) SYMF(dum1, g_dummy1)
    SYMF(invn_e2, g_invn_e2) SYMF(dum2, g_dummy2)
    SYMF(invee, g_invee)
    SYMF(fsc, g_fsc)     SYMF(fsh, g_fsh)
    SYMF(cap, g_colabsPart)
    SYMF(invcol_s, g_invcol_s) SYMF(invcol_q, g_invcol_q)
    SYMF(ax, g_ax)       SYMF(ux, g_ux)
    SYMF(Tt, g_Tt)       SYMF(Tp, g_Tpart)
    SYMF(e1, g_emb1)     SYMF(e2, g_emb2)
    SYMF(r2, g_r2)       SYMF(y2, g_y2)
    SYMF(invr, g_inv_rmax)
    unsigned int* rmo; { void* _p=nullptr; cudaGetSymbolAddress(&_p, g_rmax_ord); rmo=(unsigned int*)_p; }

    const float* xq = xr + CHW;

    // conv1 (fp32) -> BN -> relu
    gemm_k<0,0><<<dim3(32,2,2),256>>>(256,4096,512, conv1w,512,0, x,4096,(size_t)512*4096,
        xr,(size_t)CHW, nullptr,nullptr, 0, 1.f,nullptr, nullptr,nullptr,0);
    convbn_stats<<<256,256>>>(xr, bn1g, bn1b, bnsc, bnsh);
    bnrelu_k<<<2*CHW/256,256>>>(xr, bnsc, bnsh);

    // ---- layer 0, graph q -> emb2 (batched ax/ux lands in the ncu slot) ----
    gemm_t32<<<dim3(4,32,2),256>>>(4096,512,256, xq,256, nullptr,0, g0aw,256, ax,
        nullptr, 1.f,nullptr, g0ab, nullptr,1, g0uw, g0ub, ux);
    pos_kernel<<<CHW/256,256>>>(xr, mask, pos);
    colred_part<<<CRP,256>>>(xq, 256, 256, pS, pQ);
    colred_fin<<<1,256>>>(pS, pQ, 256, 0, nullptr,nullptr, nullptr, invn_q, invn2_q, nullptr);
    gram_tf32<<<dim3(16,32),256>>>(256, xq,256,invn_q, xq,256,invn_q, cap, nullptr);
    colabs_fin<<<16,256>>>(cap, invcol_q);
    gemm_k<1,0><<<dim3(4,2,16),256>>>(256,512,4096, xq,256,0, ax,512,0, Tp,0,
        nullptr,invcol_q, 256, 1.f,nullptr, nullptr,nullptr,0);
    splitk_reduceT<<<dim3(8,16),256>>>(16, 256, 512, Tp, Tt);
    gemm_t32<<<dim3(4,32,1),256>>>(4096,512,256, xq,256, nullptr,0, Tt,256, e2,
        invn2_q, 1.f,nullptr, nullptr, ux,0, nullptr,nullptr,nullptr);

    // ---- layer 0, graph s -> emb1 ----
    gemm_t32<<<dim3(4,32,2),256>>>(4096,512,256, pos,256, nullptr,0, g0aw,256, ax,
        nullptr, 1.f,nullptr, g0ab, nullptr,1, g0uw, g0ub, ux);
    colred_part<<<CRP,256>>>(pos, 256, 256, pS, pQ);
    colred_fin<<<1,256>>>(pS, pQ, 256, 0, nullptr,nullptr, nullptr, invn_s, invn2_s, nullptr);
    gram_tf32<<<dim3(16,32),256>>>(256, pos,256,invn_s, pos,256,invn_s, cap, nullptr);
    colabs_fin<<<16,256>>>(cap, invcol_s);
    gemm_k<1,0><<<dim3(4,2,16),256>>>(256,512,4096, pos,256,0, ax,512,0, Tp,0,
        nullptr,invcol_s, 256, 1.f,nullptr, nullptr,nullptr,0);
    splitk_reduceT<<<dim3(8,16),256>>>(16, 256, 512, Tp, Tt);
    gemm_t32<<<dim3(4,32,1),256>>>(4096,512,256, pos,256, nullptr,0, Tt,256, e1,
        invn2_s, 1.f,nullptr, nullptr, ux,0, nullptr,nullptr,nullptr);

    // ---- R = adjacency(emb1, emb2) ----
    colred_part<<<CRP,256>>>(e1, 512, 512, pS, pQ);
    colred_fin<<<2,256>>>(pS, pQ, 512, 0, nullptr,nullptr, nullptr, invn_e1, dum1, nullptr);
    colred_part<<<CRP,256>>>(e2, 512, 512, pS, pQ);
    colred_fin<<<2,256>>>(pS, pQ, 512, 0, nullptr,nullptr, invn_e1, invn_e2, dum2, invee);
    init_rmax_k<<<1,1>>>(rmo);
    gram_tf32<<<dim3(16,32),256>>>(512, e1,512,invn_e1, e2,512,invn_e2, nullptr, rmo);
    fin_rmax_k<<<1,1>>>(rmo, invr);

    // ---- cross for emb2 ----
    gemm_k<1,0><<<dim3(4,4,16),256>>>(512,512,4096, e1,512,0, e1,512,0, Tp,0,
        nullptr,nullptr, 256, 1.f,nullptr, nullptr,nullptr,0);
    splitk_reduceT<<<dim3(16,16),256>>>(16, 512, 512, Tp, Tt);
    gemm_t32<<<dim3(4,32,1),256>>>(4096,512,512, e2,512, nullptr,0, Tt,512, r2,
        invee, 1.f,invr, nullptr, nullptr,0, nullptr,nullptr,nullptr);
    // y2 = [e2 | r2] @ cgw^T + cgb  (fused concat-K GEMM, K=1024)
    gemm_t32<<<dim3(4,32,1),256>>>(4096,512,1024, e2,512, r2,512, cgw,1024, y2,
        nullptr, 1.f,nullptr, cgb, nullptr,0, nullptr,nullptr,nullptr);
    colred_part<<<CRP,256>>>(y2, 512, 512, pS, pQ);
    colred_fin<<<2,256>>>(pS, pQ, 512, 1, cgbng, cgbnb, nullptr, fsc, fsh, nullptr);
    bnapply_k<<<NN*512/256,256>>>(y2, fsc, fsh, e2);

    // ---- layer 1 for emb2 ----
    gemm_t32<<<dim3(4,32,2),256>>>(4096,512,512, e2,512, nullptr,0, g1aw,512, ax,
        nullptr, 1.f,nullptr, g1ab, nullptr,1, g1uw, g1ub, ux);
    gemm_k<1,0><<<dim3(4,2,16),256>>>(256,512,4096, xq,256,0, ax,512,0, Tp,0,
        nullptr,invcol_q, 256, 1.f,nullptr, nullptr,nullptr,0);
    splitk_reduceT<<<dim3(8,16),256>>>(16, 256, 512, Tp, Tt);
    gemm_t32<<<dim3(4,32,1),256>>>(4096,512,256, xq,256, nullptr,0, Tt,256, out,
        invn2_q, 1.f,nullptr, nullptr, ux,0, nullptr,nullptr,nullptr);
}

// round 16
// speedup vs baseline: 1.0830x; 1.0830x over previous
#include <cuda_runtime.h>
#include <math.h>

#define NN 4096
#define C1 256
#define C2 512
#define CHW (256*4096)
#define CRP 256   // colred_part blocks

// ---------------- static scratch (no allocations allowed) ----------------
__device__ float g_xr[2*CHW];
__device__ float g_pos[CHW];
__device__ float g_bnsc[C1], g_bnsh[C1];
__device__ float g_partS[2*CRP*C2], g_partQ[2*CRP*C2];
__device__ float g_invn_s[C1], g_invn2_s[C1];
__device__ float g_invn_q[C1], g_invn2_q[C1];
__device__ float g_invn_e1[C2], g_dummy1[C2];
__device__ float g_invn_e2[C2], g_dummy2[C2];
__device__ float g_invee[C2];
__device__ float g_fsc[C2], g_fsh[C2];
__device__ float g_colabsPart[2*32*NN];
__device__ float g_invcol_s[NN], g_invcol_q[NN];
__device__ unsigned int g_rmax_ord;
__device__ float g_inv_rmax;
__device__ float g_ax[NN*C2];
__device__ float g_ux[NN*C2];
__device__ float g_ax2[NN*C2];
__device__ float g_ux2[NN*C2];
__device__ float g_Tt[C2*C2];
__device__ float g_Tt2[C2*C2];
__device__ float g_Tpart[16*C2*C2];
__device__ float g_emb1[NN*C2];
__device__ float g_emb2[NN*C2];
__device__ float g_r2[NN*C2];
__device__ float g_y2[NN*C2];

__device__ __forceinline__ unsigned ord_of_float(float f) {
    unsigned u = __float_as_uint(f);
    return (u & 0x80000000u) ? ~u : (u | 0x80000000u);
}
__device__ __forceinline__ unsigned f2tf32(float v) {
    unsigned r; asm("cvt.rna.tf32.f32 %0, %1;" : "=r"(r) : "f"(v)); return r;
}
__device__ __forceinline__ void mma_tf32(float* d, const unsigned* a, const unsigned* b) {
    asm volatile("mma.sync.aligned.m16n8k8.row.col.f32.tf32.tf32.f32 "
        "{%0,%1,%2,%3}, {%4,%5,%6,%7}, {%8,%9}, {%0,%1,%2,%3};"
        : "+f"(d[0]), "+f"(d[1]), "+f"(d[2]), "+f"(d[3])
        : "r"(a[0]), "r"(a[1]), "r"(a[2]), "r"(a[3]), "r"(b[0]), "r"(b[1]));
}

// per-z parameter set for the tf32 GEMM
struct GT {
    const float* A; const float* ksA; const float* B;
    const float* bias; const float* addMat; float* C;
};

// ---------------- generic SGEMM 128x128x16, double-buffered smem ----------------
// splitLen>0: z in [0,16) slices of K on (A,B,ksB); z in [16,32) on (Ab,Bb,ksBb).
// Partials at C + z*M*N. splitLen==0: grid.z = batch with strides sA/sB/sC.
template<int TA, int TB>
__global__ void __launch_bounds__(256)
gemm_k(int M, int N, int K,
       const float* __restrict__ A, int lda, size_t sA,
       const float* __restrict__ B, int ldb, size_t sB,
       float* __restrict__ C, size_t sC,
       const float* __restrict__ ksA, const float* __restrict__ ksB,
       int splitLen, float alphaS, const float* __restrict__ alphaPtr,
       const float* __restrict__ bias,
       const float* __restrict__ addMat, int doRelu,
       const float* __restrict__ Ab, const float* __restrict__ Bb,
       const float* __restrict__ ksBb)
{
    __shared__ float As[2][16][128];
    __shared__ float Bs[2][16][128];
    const int tid = threadIdx.x;
    const int tx = tid & 15, ty = tid >> 4;
    const int n0 = blockIdx.x * 128;
    const int m0 = blockIdx.y * 128;
    const int z  = blockIdx.z;

    int k0, kEnd;
    if (splitLen > 0) {
        if (z >= 16) { A = Ab; B = Bb; ksB = ksBb; }
        k0 = (z & 15) * splitLen; kEnd = k0 + splitLen;
        C += (size_t)z * M * N;
    }
    else { k0 = 0; kEnd = K; A += (size_t)z*sA; B += (size_t)z*sB; C += (size_t)z*sC; }

    float acc[8][8];
    #pragma unroll
    for (int i=0;i<8;i++)
        #pragma unroll
        for (int j=0;j<8;j++) acc[i][j]=0.f;

    float4 rA0, rA1, rB0, rB1;

    auto loadA = [&](int kk, float4& a0, float4& a1) {
        if (TA == 0) {
            int m = tid >> 1, k8 = (tid & 1) * 8;
            const float* src = A + (size_t)(m0+m)*lda + kk + k8;
            a0 = *(const float4*)src; a1 = *(const float4*)(src+4);
        } else {
            int k = tid >> 4, m8 = (tid & 15) * 8;
            const float* src = A + (size_t)(kk+k)*lda + m0 + m8;
            a0 = *(const float4*)src; a1 = *(const float4*)(src+4);
        }
    };
    auto loadB = [&](int kk, float4& b0, float4& b1) {
        if (TB == 0) {
            int k = tid >> 4, n8 = (tid & 15) * 8;
            const float* src = B + (size_t)(kk+k)*ldb + n0 + n8;
            b0 = *(const float4*)src; b1 = *(const float4*)(src+4);
        } else {
            int n = tid >> 1, k8 = (tid & 1) * 8;
            const float* src = B + (size_t)(n0+n)*ldb + kk + k8;
            b0 = *(const float4*)src; b1 = *(const float4*)(src+4);
        }
    };
    auto storeA = [&](int buf, int kk, const float4& a0, const float4& a1) {
        float vv[8] = {a0.x,a0.y,a0.z,a0.w,a1.x,a1.y,a1.z,a1.w};
        if (TA == 0) {
            int m = tid >> 1, k8 = (tid & 1) * 8;
            #pragma unroll
            for (int i=0;i<8;i++) {
                float s = ksA ? ksA[kk+k8+i] : 1.f;
                As[buf][k8+i][m] = vv[i]*s;
            }
        } else {
            int k = tid >> 4, m8 = (tid & 15) * 8;
            float s = ksA ? ksA[kk+k] : 1.f;
            #pragma unroll
            for (int i=0;i<8;i++) As[buf][k][m8+i] = vv[i]*s;
        }
    };
    auto storeB = [&](int buf, int kk, const float4& b0, const float4& b1) {
        float vv[8] = {b0.x,b0.y,b0.z,b0.w,b1.x,b1.y,b1.z,b1.w};
        if (TB == 0) {
            int k = tid >> 4, n8 = (tid & 15) * 8;
            float s = ksB ? ksB[kk+k] : 1.f;
            #pragma unroll
            for (int i=0;i<8;i++) Bs[buf][k][n8+i] = vv[i]*s;
        } else {
            int n = tid >> 1, k8 = (tid & 1) * 8;
            #pragma unroll
            for (int i=0;i<8;i++) {
                float s = ksB ? ksB[kk+k8+i] : 1.f;
                Bs[buf][k8+i][n] = vv[i]*s;
            }
        }
    };

    loadA(k0, rA0, rA1); loadB(k0, rB0, rB1);
    storeA(0, k0, rA0, rA1); storeB(0, k0, rB0, rB1);
    __syncthreads();

    int buf = 0;
    for (int kk = k0; kk < kEnd; kk += 16) {
        const bool hasNext = (kk + 16) < kEnd;
        if (hasNext) { loadA(kk+16, rA0, rA1); loadB(kk+16, rB0, rB1); }
        #pragma unroll
        for (int k=0;k<16;k++) {
            float4 a0 = *(const float4*)&As[buf][k][ty*4];
            float4 a1 = *(const float4*)&As[buf][k][ty*4+64];
            float4 b0 = *(const float4*)&Bs[buf][k][tx*4];
            float4 b1 = *(const float4*)&Bs[buf][k][tx*4+64];
            float a[8] = {a0.x,a0.y,a0.z,a0.w,a1.x,a1.y,a1.z,a1.w};
            float b[8] = {b0.x,b0.y,b0.z,b0.w,b1.x,b1.y,b1.z,b1.w};
            #pragma unroll
            for (int i=0;i<8;i++)
                #pragma unroll
                for (int j=0;j<8;j++)
                    acc[i][j] += a[i]*b[j];
        }
        if (hasNext) {
            storeA(buf^1, kk+16, rA0, rA1);
            storeB(buf^1, kk+16, rB0, rB1);
            __syncthreads();
            buf ^= 1;
        }
    }

    if (splitLen > 0) {
        #pragma unroll
        for (int i=0;i<8;i++) {
            int m = m0 + ty*4 + (i&3) + ((i>>2)<<6);
            #pragma unroll
            for (int j=0;j<8;j++) {
                int n = n0 + tx*4 + (j&3) + ((j>>2)<<6);
                C[(size_t)m*N + n] = acc[i][j];
            }
        }
        return;
    }
    float alpha = alphaS * (alphaPtr ? *alphaPtr : 1.f);
    #pragma unroll
    for (int i=0;i<8;i++) {
        int m = m0 + ty*4 + (i&3) + ((i>>2)<<6);
        #pragma unroll
        for (int j=0;j<8;j++) {
            int n = n0 + tx*4 + (j&3) + ((j>>2)<<6);
            float v = acc[i][j]*alpha;
            if (bias)   v += bias[n];
            if (addMat) v += addMat[(size_t)m*N + n];
            if (doRelu) v = fmaxf(v, 0.f);
            C[(size_t)m*N + n] = v;
        }
    }
}

// --- tf32x3 tensor GEMM (PROVEN R13 body): C = act(alpha*(A*ksA)@B^T+bias+add)
// Block 128x128, 256 thr, 8 warps (2m x 4n), warp 64x32, k-tile 8, hi/lo smem.
// blockIdx.z selects one of 4 GT parameter sets. A2/Ksplit: fused concat-K (z=0).
__global__ void __launch_bounds__(256, 2)
gemm_t32(int M, int N, int K, int lda, int ldb,
         GT g0, GT g1, GT g2, GT g3,
         const float* __restrict__ A2, int Ksplit,
         float alphaS, const float* __restrict__ alphaPtr, int doRelu)
{
    __shared__ unsigned sh[8192];
    const int tid = threadIdx.x, lane = tid & 31, wid = tid >> 5;
    const int wm = wid >> 2, wn = wid & 3;
    const int n0 = blockIdx.x * 128, m0 = blockIdx.y * 128;
    const int r = lane >> 2, c = lane & 3;
    const bool isA = tid < 128;
    const int row = isA ? tid : tid - 128;

    GT P = g0;
    if (blockIdx.z == 1) P = g1;
    else if (blockIdx.z == 2) P = g2;
    else if (blockIdx.z == 3) P = g3;

    float acc[4][4][4];
    #pragma unroll
    for (int mf=0; mf<4; mf++)
        #pragma unroll
        for (int nf=0; nf<4; nf++)
            #pragma unroll
            for (int q=0; q<4; q++) acc[mf][nf][q] = 0.f;

    float4 v0, v1;
    auto ldg = [&](int kk) {
        const float* p;
        if (isA) {
            const float* base = P.A; int kx = kk;
            if (A2 && kk >= Ksplit) { base = A2; kx = kk - Ksplit; }
            p = base + (size_t)(m0+row)*lda + kx;
        } else {
            p = P.B + (size_t)(n0+row)*ldb + kk;
        }
        v0 = *(const float4*)p; v1 = *(const float4*)(p+4);
    };
    auto sts = [&](int buf, int kk) {
        float a[8] = {v0.x,v0.y,v0.z,v0.w,v1.x,v1.y,v1.z,v1.w};
        if (isA && P.ksA) {
            #pragma unroll
            for (int i=0;i<8;i++) a[i] *= P.ksA[kk+i];
        }
        unsigned h[8], l[8];
        #pragma unroll
        for (int i=0;i<8;i++) {
            h[i] = f2tf32(a[i]);
            l[i] = f2tf32(a[i] - __uint_as_float(h[i]));
        }
        unsigned* hp = &sh[(isA ? 0 : 4096) + buf*1024 + row*8];
        unsigned* lp = hp + 2048;
        *(uint4*)hp     = make_uint4(h[0],h[4],h[1],h[5]);
        *(uint4*)(hp+4) = make_uint4(h[2],h[6],h[3],h[7]);
        *(uint4*)lp     = make_uint4(l[0],l[4],l[1],l[5]);
        *(uint4*)(lp+4) = make_uint4(l[2],l[6],l[3],l[7]);
    };

    ldg(0); sts(0, 0);
    __syncthreads();

    int buf = 0;
    for (int kk = 0; kk < K; kk += 8) {
        const bool nxt = (kk + 8) < K;
        if (nxt) ldg(kk + 8);
        const unsigned* Ah = &sh[buf*1024];
        const unsigned* Al = Ah + 2048;
        const unsigned* Bh = &sh[4096 + buf*1024];
        const unsigned* Bl = Bh + 2048;
        unsigned afh[4][4], afl[4][4], bfh[4][2], bfl[4][2];
        #pragma unroll
        for (int mf=0; mf<4; mf++) {
            int m = wm*64 + mf*16;
            uint2 p = *(const uint2*)&Ah[(m+r)*8 + 2*c];
            uint2 q = *(const uint2*)&Ah[(m+r+8)*8 + 2*c];
            afh[mf][0] = p.x; afh[mf][1] = q.x; afh[mf][2] = p.y; afh[mf][3] = q.y;
            uint2 pl = *(const uint2*)&Al[(m+r)*8 + 2*c];
            uint2 ql = *(const uint2*)&Al[(m+r+8)*8 + 2*c];
            afl[mf][0] = pl.x; afl[mf][1] = ql.x; afl[mf][2] = pl.y; afl[mf][3] = ql.y;
        }
        #pragma unroll
        for (int nf=0; nf<4; nf++) {
            uint2 p  = *(const uint2*)&Bh[(wn*32 + nf*8 + r)*8 + 2*c];
            bfh[nf][0] = p.x; bfh[nf][1] = p.y;
            uint2 pl = *(const uint2*)&Bl[(wn*32 + nf*8 + r)*8 + 2*c];
            bfl[nf][0] = pl.x; bfl[nf][1] = pl.y;
        }
        #pragma unroll
        for (int mf=0; mf<4; mf++)
            #pragma unroll
            for (int nf=0; nf<4; nf++) {
                mma_tf32(acc[mf][nf], afl[mf], bfh[nf]);
                mma_tf32(acc[mf][nf], afh[mf], bfl[nf]);
                mma_tf32(acc[mf][nf], afh[mf], bfh[nf]);
            }
        if (nxt) {
            sts(buf^1, kk + 8);
            __syncthreads();
            buf ^= 1;
        }
    }

    float alpha = alphaS * (alphaPtr ? *alphaPtr : 1.f);
    #pragma unroll
    for (int mf=0; mf<4; mf++) {
        #pragma unroll
        for (int h=0; h<2; h++) {
            int orow = m0 + wm*64 + mf*16 + r + h*8;
            #pragma unroll
            for (int nf=0; nf<4; nf++) {
                int col = n0 + wn*32 + nf*8 + 2*c;
                float w0 = acc[mf][nf][h*2]   * alpha;
                float w1 = acc[mf][nf][h*2+1] * alpha;
                if (P.bias)   { w0 += P.bias[col]; w1 += P.bias[col+1]; }
                if (P.addMat) { w0 += P.addMat[(size_t)orow*N + col];
                                w1 += P.addMat[(size_t)orow*N + col + 1]; }
                if (doRelu) { w0 = fmaxf(w0, 0.f); w1 = fmaxf(w1, 0.f); }
                *(float2*)&P.C[(size_t)orow*N + col] = make_float2(w0, w1);
            }
        }
    }
}

// ---- split-K reduce + transpose: out[n*M+m] = sum_z part[z][m][n], 32x32 tiles.
// blockIdx.z selects part slice (z*S*M*N) and output (out0/out1).
__global__ void splitk_reduceT(int S, int M, int N,
                               const float* __restrict__ part,
                               float* __restrict__ out0, float* __restrict__ out1)
{
    __shared__ float t[32][33];
    part += (size_t)blockIdx.z * S * M * N;
    float* out = blockIdx.z ? out1 : out0;
    int m0 = blockIdx.x*32, n0 = blockIdx.y*32;
    int g = threadIdx.x >> 5, ln = threadIdx.x & 31;
    #pragma unroll
    for (int i=0;i<4;i++) {
        int m = g*4 + i;
        float s = 0.f;
        #pragma unroll 4
        for (int z=0;z<16;z++)
            s += part[((size_t)z*M + m0+m)*N + n0+ln];
        t[m][ln] = s;
    }
    __syncthreads();
    #pragma unroll
    for (int i=0;i<4;i++) {
        int n = g*4 + i;
        out[(size_t)(n0+n)*M + m0 + ln] = t[ln][n];
    }
}

// ------------- streamed Gram stats via tf32 mma: G = (A*scA)(B*scB)^T ---------
// blockIdx.z==1 switches to the second input set. colAbsPart offset by z*32*NN.
__global__ void __launch_bounds__(256)
gram_tf32(int Cc,
          const float* __restrict__ A, int lda, const float* __restrict__ scA,
          const float* __restrict__ Bm, int ldb, const float* __restrict__ scB,
          const float* __restrict__ A1, const float* __restrict__ scA1,
          const float* __restrict__ B1, const float* __restrict__ scB1,
          float* __restrict__ colAbsPart, unsigned int* __restrict__ maxOrd)
{
    __shared__ unsigned sh[12288];   // exactly 48KB
    const int tid = threadIdx.x, lane = tid & 31, wid = tid >> 5;
    const int wm = wid >> 2, wn = wid & 3;
    const int m0 = blockIdx.x * 256;   // cols (Bm rows)
    const int n0 = blockIdx.y * 128;   // rows (A rows)
    const int r = lane >> 2, c = lane & 3;
    const int ar = tid >> 1, asl = tid & 1;

    if (blockIdx.z == 1) { A = A1; scA = scA1; Bm = B1; scB = scB1; }

    float acc[4][8][4];
    #pragma unroll
    for (int mf=0; mf<4; mf++)
        #pragma unroll
        for (int nf=0; nf<8; nf++)
            #pragma unroll
            for (int q=0; q<4; q++) acc[mf][nf][q] = 0.f;

    float4 vA0, vA1, vB0, vB1, vB2, vB3;
    auto ldg = [&](int cc) {
        const float* pa = A + (size_t)(n0+ar)*lda + cc + asl*8;
        vA0 = *(const float4*)pa; vA1 = *(const float4*)(pa+4);
        const float* pb = Bm + (size_t)(m0+tid)*ldb + cc;
        vB0 = *(const float4*)pb;     vB1 = *(const float4*)(pb+4);
        vB2 = *(const float4*)(pb+8); vB3 = *(const float4*)(pb+12);
    };
    auto sts = [&](int buf, int cc) {
        float a[8] = {vA0.x,vA0.y,vA0.z,vA0.w,vA1.x,vA1.y,vA1.z,vA1.w};
        #pragma unroll
        for (int i=0;i<8;i++) a[i] *= scA[cc + asl*8 + i];
        uint4 u0 = make_uint4(f2tf32(a[0]), f2tf32(a[4]), f2tf32(a[1]), f2tf32(a[5]));
        uint4 u1 = make_uint4(f2tf32(a[2]), f2tf32(a[6]), f2tf32(a[3]), f2tf32(a[7]));
        unsigned* ab = &sh[buf*2048 + asl*1024 + ar*8];
        *(uint4*)ab = u0; *(uint4*)(ab+4) = u1;
        float b[16] = {vB0.x,vB0.y,vB0.z,vB0.w, vB1.x,vB1.y,vB1.z,vB1.w,
                       vB2.x,vB2.y,vB2.z,vB2.w, vB3.x,vB3.y,vB3.z,vB3.w};
        #pragma unroll
        for (int i=0;i<16;i++) b[i] *= scB[cc + i];
        uint4 w0 = make_uint4(f2tf32(b[0]),  f2tf32(b[4]),  f2tf32(b[1]),  f2tf32(b[5]));
        uint4 w1 = make_uint4(f2tf32(b[2]),  f2tf32(b[6]),  f2tf32(b[3]),  f2tf32(b[7]));
        uint4 w2 = make_uint4(f2tf32(b[8]),  f2tf32(b[12]), f2tf32(b[9]),  f2tf32(b[13]));
        uint4 w3 = make_uint4(f2tf32(b[10]), f2tf32(b[14]), f2tf32(b[11]), f2tf32(b[15]));
        unsigned* bb = &sh[4096 + buf*4096 + tid*8];
        *(uint4*)bb = w0; *(uint4*)(bb+4) = w1;
        *(uint4*)(bb+2048) = w2; *(uint4*)(bb+2048+4) = w3;
    };

    ldg(0); sts(0, 0);
    __syncthreads();

    int buf = 0;
    for (int cc = 0; cc < Cc; cc += 16) {
        const bool nxt = (cc + 16) < Cc;
        if (nxt) ldg(cc + 16);
        #pragma unroll
        for (int s=0; s<2; s++) {
            const unsigned* Ab = &sh[buf*2048 + s*1024];
            const unsigned* Bb = &sh[4096 + buf*4096 + s*2048];
            unsigned af[4][4];
            #pragma unroll
            for (int mf=0; mf<4; mf++) {
                int m = wm*64 + mf*16;
                uint2 p = *(const uint2*)&Ab[(m+r)*8 + 2*c];
                uint2 q = *(const uint2*)&Ab[(m+r+8)*8 + 2*c];
                af[mf][0] = p.x; af[mf][1] = q.x; af[mf][2] = p.y; af[mf][3] = q.y;
            }
            unsigned bf[8][2];
            #pragma unroll
            for (int nf=0; nf<8; nf++) {
                uint2 p = *(const uint2*)&Bb[(wn*64 + nf*8 + r)*8 + 2*c];
                bf[nf][0] = p.x; bf[nf][1] = p.y;
            }
            #pragma unroll
            for (int mf=0; mf<4; mf++)
                #pragma unroll
                for (int nf=0; nf<8; nf++)
                    mma_tf32(acc[mf][nf], af[mf], bf[nf]);
        }
        if (nxt) {
            sts(buf^1, cc + 16);
            __syncthreads();
            buf ^= 1;
        }
    }
    float* cw  = (float*)&sh[4096];          // [8][64]
    float* wmx = (float*)&sh[4096 + 512];    // [8]

    if (colAbsPart) {
        #pragma unroll
        for (int nf=0; nf<8; nf++) {
            float s0 = 0.f, s1 = 0.f;
            #pragma unroll
            for (int mf=0; mf<4; mf++) {
                s0 += fabsf(acc[mf][nf][0]) + fabsf(acc[mf][nf][2]);
                s1 += fabsf(acc[mf][nf][1]) + fabsf(acc[mf][nf][3]);
            }
            #pragma unroll
            for (int off=4; off<32; off<<=1) {
                s0 += __shfl_xor_sync(0xffffffffu, s0, off);
                s1 += __shfl_xor_sync(0xffffffffu, s1, off);
            }
            if (lane < 4) {
                cw[wid*64 + nf*8 + 2*lane    ] = s0;
                cw[wid*64 + nf*8 + 2*lane + 1] = s1;
            }
        }
        __syncthreads();
        {
            int wn2 = tid >> 6, j = tid & 63;
            float s = cw[wn2*64 + j] + cw[(4+wn2)*64 + j];
            colAbsPart[(size_t)blockIdx.z*32*NN + (size_t)blockIdx.y*NN + m0 + tid] = s;
        }
    }
    if (maxOrd) {
        float mx = -3.4e38f;
        #pragma unroll
        for (int mf=0; mf<4; mf++)
            #pragma unroll
            for (int nf=0; nf<8; nf++)
                #pragma unroll
                for (int q=0; q<4; q++) mx = fmaxf(mx, acc[mf][nf][q]);
        #pragma unroll
        for (int off=16; off; off>>=1)
            mx = fmaxf(mx, __shfl_xor_sync(0xffffffffu, mx, off));
        if (lane == 0) wmx[wid] = mx;
        __syncthreads();
        if (tid == 0) {
            float m2 = wmx[0];
            #pragma unroll
            for (int t=1;t<8;t++) m2 = fmaxf(m2, wmx[t]);
            atomicMax(maxOrd, ord_of_float(m2));
        }
    }
}

// ---------------- small kernels ----------------
__global__ void convbn_stats(const float* __restrict__ xr, const float* __restrict__ g,
                             const float* __restrict__ b, float* sc, float* sh)
{
    int o = blockIdx.x;
    const float* p0 = xr + (size_t)o*4096;
    const float* p1 = xr + (size_t)CHW + (size_t)o*4096;
    float s=0.f, q=0.f;
    for (int i = threadIdx.x; i < 4096; i += 256) {
        float v = p0[i]; s += v; q += v*v;
        v = p1[i];       s += v; q += v*v;
    }
    __shared__ float ss[256], sq[256];
    ss[threadIdx.x]=s; sq[threadIdx.x]=q; __syncthreads();
    for (int off=128; off; off>>=1) {
        if (threadIdx.x < off) { ss[threadIdx.x]+=ss[threadIdx.x+off]; sq[threadIdx.x]+=sq[threadIdx.x+off]; }
        __syncthreads();
    }
    if (threadIdx.x == 0) {
        float mean = ss[0]/8192.f;
        float var  = sq[0]/8192.f - mean*mean;
        float scl  = g[o]*rsqrtf(var + 1e-5f);
        sc[o] = scl; sh[o] = b[o] - mean*scl;
    }
}

__global__ void bnrelu_k(float* x, const float* sc, const float* sh) {
    int i = blockIdx.x*256 + threadIdx.x;
    int o = (i >> 12) & 255;
    x[i] = fmaxf(x[i]*sc[o] + sh[o], 0.f);
}

__global__ void pos_kernel(const float* __restrict__ x0, const float* __restrict__ mask,
                           float* __restrict__ out)
{
    int gid = blockIdx.x*256 + threadIdx.x;
    int c = gid >> 12, p = gid & 4095;
    int i = p >> 6, j = p & 63;
    const float* img = x0 + (size_t)c*4096;
    float yd = i * (511.f/63.f);
    int Y0 = min((int)yd, 511), Y1 = min(Y0+1, 511);
    float wy = yd - (float)Y0;
    float xd = j * (511.f/63.f);
    int X0 = min((int)xd, 511), X1 = min(X0+1, 511);
    float wx = xd - (float)X0;
    int Ys[2]={Y0,Y1}; float wys[2]={1.f-wy, wy};
    int Xs[2]={X0,X1}; float wxs[2]={1.f-wx, wx};
    float acc = 0.f;
    #pragma unroll
    for (int a=0;a<2;a++) {
        int Y = Ys[a];
        float yu = Y*(63.f/511.f);
        int a0 = min((int)yu, 63), a1 = min(a0+1, 63);
        float wa = yu - (float)a0;
        #pragma unroll
        for (int b=0;b<2;b++) {
            int X = Xs[b];
            float xu = X*(63.f/511.f);
            int b0 = min((int)xu, 63), b1 = min(b0+1, 63);
            float wb = xu - (float)b0;
            float v = (img[a0*64+b0]*(1.f-wb) + img[a0*64+b1]*wb)*(1.f-wa)
                    + (img[a1*64+b0]*(1.f-wb) + img[a1*64+b1]*wb)*wa;
            acc += wys[a]*wxs[b]*mask[Y*512+X]*v;
        }
    }
    out[gid] = acc;
}

// z selects input X0/X1; partials at pS/pQ + z*CRP*C.
__global__ void colred_part(const float* __restrict__ X0, const float* __restrict__ X1,
                            int ld, int C,
                            float* __restrict__ pS, float* __restrict__ pQ)
{
    const float* X = blockIdx.z ? X1 : X0;
    size_t off = (size_t)blockIdx.z * CRP * C;
    int r0 = blockIdx.x * (NN/CRP);
    int c0 = threadIdx.x, c1 = threadIdx.x + 256;
    float s0=0,q0=0,s1=0,q1=0;
    #pragma unroll 4
    for (int r=0;r<NN/CRP;r++) {
        const float* row = X + (size_t)(r0+r)*ld;
        float v = row[c0]; s0 += v; q0 += v*v;
        if (C > 256) { float w = row[c1]; s1 += w; q1 += w*w; }
    }
    pS[off + blockIdx.x*C + c0] = s0; pQ[off + blockIdx.x*C + c0] = q0;
    if (C > 256) { pS[off + blockIdx.x*C + c1] = s1; pQ[off + blockIdx.x*C + c1] = q1; }
}

// mode 0: o1=1/max(||col||,eps), o2=o1^2.  mode 1: BN scale/shift over 4096 rows.
// z==1 switches to o1b/o2b and partial slice 1.
__global__ void colred_fin(const float* __restrict__ pS, const float* __restrict__ pQ,
                           int C, int mode,
                           const float* g, const float* b,
                           float* o1, float* o2, float* o1b, float* o2b)
{
    if (blockIdx.z == 1) { o1 = o1b; o2 = o2b; }
    size_t off = (size_t)blockIdx.z * CRP * C;
    int c = blockIdx.x*256 + threadIdx.x;
    if (c >= C) return;
    float S=0.f, Q=0.f;
    #pragma unroll 4
    for (int z=0; z<CRP; z++) { S += pS[off + z*C+c]; Q += pQ[off + z*C+c]; }
    if (mode == 0) {
        float inv = 1.f / fmaxf(sqrtf(Q), 1e-12f);
        o1[c] = inv; o2[c] = inv*inv;
    } else {
        float mean = S*(1.f/4096.f);
        float var  = Q*(1.f/4096.f) - mean*mean;
        float sc   = g[c]*rsqrtf(var + 1e-5f);
        o1[c] = sc; o2[c] = b[c] - mean*sc;
    }
}

__global__ void colabs_fin(const float* __restrict__ part,
                           float* __restrict__ inv0, float* __restrict__ inv1)
{
    const float* p = part + (size_t)blockIdx.z*32*NN;
    float* inv = blockIdx.z ? inv1 : inv0;
    int m = blockIdx.x*256 + threadIdx.x;
    float s = 0.f;
    #pragma unroll 4
    for (int z=0; z<32; z++) s += p[z*NN + m];
    inv[m] = 1.f / fmaxf(s, 1e-12f);
}

__global__ void vecmul_k(const float* a, const float* b, float* o) {
    int i = blockIdx.x*256 + threadIdx.x;
    o[i] = a[i]*b[i];
}

__global__ void init_rmax_k(unsigned int* p) { *p = 0u; }
__global__ void fin_rmax_k(const unsigned int* p, float* o) {
    unsigned u = *p;
    unsigned f = (u & 0x80000000u) ? (u & 0x7fffffffu) : ~u;
    *o = 1.f / __uint_as_float(f);
}

__global__ void bnapply_k(const float* y, const float* sc, const float* sh, float* o) {
    int i = blockIdx.x*256 + threadIdx.x;
    int c = i & 511;
    o[i] = fmaxf(y[i]*sc[c] + sh[c], 0.f);
}

// ---------------- host ----------------
#define SYMF(name, sym) float* name; { void* _p=nullptr; cudaGetSymbolAddress(&_p, sym); name=(float*)_p; }

extern "C" void kernel_launch(void* const* d_in, const int* in_sizes, int n_in,
                              void* d_out, int out_size)
{
    const float* x      = (const float*)d_in[0];
    const float* mask   = (const float*)d_in[1];
    const float* conv1w = (const float*)d_in[2];
    const float* bn1g   = (const float*)d_in[3];
    const float* bn1b   = (const float*)d_in[4];
    const float* g0aw   = (const float*)d_in[5];
    const float* g0ab   = (const float*)d_in[6];
    const float* g0uw   = (const float*)d_in[7];
    const float* g0ub   = (const float*)d_in[8];
    const float* g1aw   = (const float*)d_in[9];
    const float* g1ab   = (const float*)d_in[10];
    const float* g1uw   = (const float*)d_in[11];
    const float* g1ub   = (const float*)d_in[12];
    const float* cgw    = (const float*)d_in[13];
    const float* cgb    = (const float*)d_in[14];
    const float* cgbng  = (const float*)d_in[15];
    const float* cgbnb  = (const float*)d_in[16];
    float* out = (float*)d_out;

    SYMF(xr, g_xr)       SYMF(pos, g_pos)
    SYMF(bnsc, g_bnsc)   SYMF(bnsh, g_bnsh)
    SYMF(pS, g_partS)    SYMF(pQ, g_partQ)
    SYMF(invn_s, g_invn_s)   SYMF(invn2_s, g_invn2_s)
    SYMF(invn_q, g_invn_q)   SYMF(invn2_q, g_invn2_q)
    SYMF(invn_e1, g_invn_e1) SYMF(dum1, g_dummy1)
    SYMF(invn_e2, g_invn_e2) SYMF(dum2, g_dummy2)
    SYMF(invee, g_invee)
    SYMF(fsc, g_fsc)     SYMF(fsh, g_fsh)
    SYMF(cap, g_colabsPart)
    SYMF(invcol_s, g_invcol_s) SYMF(invcol_q, g_invcol_q)
    SYMF(ax, g_ax)       SYMF(ux, g_ux)
    SYMF(ax2, g_ax2)     SYMF(ux2, g_ux2)
    SYMF(Tt, g_Tt)       SYMF(Tt2, g_Tt2)  SYMF(Tp, g_Tpart)
    SYMF(e1, g_emb1)     SYMF(e2, g_emb2)
    SYMF(r2, g_r2)       SYMF(y2, g_y2)
    SYMF(invr, g_inv_rmax)
    unsigned int* rmo; { void* _p=nullptr; cudaGetSymbolAddress(&_p, g_rmax_ord); rmo=(unsigned int*)_p; }

    const float* xq = xr + CHW;
    GT gz = {nullptr,nullptr,nullptr,nullptr,nullptr,nullptr};

    // conv1 (fp32) -> BN -> relu -> pos
    gemm_k<0,0><<<dim3(32,2,2),256>>>(256,4096,512, conv1w,512,0, x,4096,(size_t)512*4096,
        xr,(size_t)CHW, nullptr,nullptr, 0, 1.f,nullptr, nullptr,nullptr,0,
        nullptr,nullptr,nullptr);
    convbn_stats<<<256,256>>>(xr, bn1g, bn1b, bnsc, bnsh);
    bnrelu_k<<<2*CHW/256,256>>>(xr, bnsc, bnsh);
    pos_kernel<<<CHW/256,256>>>(xr, mask, pos);

    // ---- layer 0, BOTH graphs batched over z ----
    {   // ax/ux for q and s in one z=4 launch (512 blocks)
        GT a0 = {xq,  nullptr, g0aw, g0ab, nullptr, ax };
        GT a1 = {xq,  nullptr, g0uw, g0ub, nullptr, ux };
        GT a2 = {pos, nullptr, g0aw, g0ab, nullptr, ax2};
        GT a3 = {pos, nullptr, g0uw, g0ub, nullptr, ux2};
        gemm_t32<<<dim3(4,32,4),256>>>(4096,512,256, 256,256, a0,a1,a2,a3,
            nullptr,0, 1.f,nullptr, 1);
    }
    colred_part<<<dim3(CRP,1,2),256>>>(xq, pos, 256, 256, pS, pQ);
    colred_fin<<<dim3(1,1,2),256>>>(pS, pQ, 256, 0, nullptr,nullptr,
        invn_q, invn2_q, invn_s, invn2_s);
    gram_tf32<<<dim3(16,32,2),256>>>(256, xq,256,invn_q, xq,256,invn_q,
        pos, invn_s, pos, invn_s, cap, nullptr);
    colabs_fin<<<dim3(16,1,2),256>>>(cap, invcol_q, invcol_s);
    gemm_k<1,0><<<dim3(4,2,32),256>>>(256,512,4096, xq,256,0, ax,512,0, Tp,0,
        nullptr,invcol_q, 256, 1.f,nullptr, nullptr,nullptr,0,
        pos, ax2, invcol_s);
    splitk_reduceT<<<dim3(8,16,2),256>>>(16, 256, 512, Tp, Tt, Tt2);
    {   // e2 / e1 finals batched (z=2)
        GT a0 = {xq,  invn2_q, Tt,  nullptr, ux,  e2};
        GT a1 = {pos, invn2_s, Tt2, nullptr, ux2, e1};
        gemm_t32<<<dim3(4,32,2),256>>>(4096,512,256, 256,256, a0,a1,a0,a0,
            nullptr,0, 1.f,nullptr, 0);
    }

    // ---- R = adjacency(emb1, emb2) ----
    colred_part<<<dim3(CRP,1,2),256>>>(e1, e2, 512, 512, pS, pQ);
    colred_fin<<<dim3(2,1,2),256>>>(pS, pQ, 512, 0, nullptr,nullptr,
        invn_e1, dum1, invn_e2, dum2);
    vecmul_k<<<2,256>>>(invn_e1, invn_e2, invee);
    init_rmax_k<<<1,1>>>(rmo);
    gram_tf32<<<dim3(16,32,1),256>>>(512, e1,512,invn_e1, e2,512,invn_e2,
        nullptr,nullptr,nullptr,nullptr, nullptr, rmo);
    fin_rmax_k<<<1,1>>>(rmo, invr);

    // ---- cross for emb2 ----
    gemm_k<1,0><<<dim3(4,4,16),256>>>(512,512,4096, e1,512,0, e1,512,0, Tp,0,
        nullptr,nullptr, 256, 1.f,nullptr, nullptr,nullptr,0,
        nullptr,nullptr,nullptr);
    splitk_reduceT<<<dim3(16,16,1),256>>>(16, 512, 512, Tp, Tt, Tt);
    {   GT a0 = {e2, invee, Tt, nullptr, nullptr, r2};
        gemm_t32<<<dim3(4,32,1),256>>>(4096,512,512, 512,512, a0,a0,a0,a0,
            nullptr,0, 1.f,invr, 0);
    }
    {   // y2 = [e2 | r2] @ cgw^T + cgb  (fused concat-K, K=1024)
        GT a0 = {e2, nullptr, cgw, cgb, nullptr, y2};
        gemm_t32<<<dim3(4,32,1),256>>>(4096,512,1024, 512,1024, a0,a0,a0,a0,
            r2,512, 1.f,nullptr, 0);
    }
    colred_part<<<dim3(CRP,1,1),256>>>(y2, y2, 512, 512, pS, pQ);
    colred_fin<<<dim3(2,1,1),256>>>(pS, pQ, 512, 1, cgbng, cgbnb,
        fsc, fsh, nullptr, nullptr);
    bnapply_k<<<NN*512/256,256>>>(y2, fsc, fsh, e2);

    // ---- layer 1 for emb2 ----
    {   GT a0 = {e2, nullptr, g1aw, g1ab, nullptr, ax};
        GT a1 = {e2, nullptr, g1uw, g1ub, nullptr, ux};
        gemm_t32<<<dim3(4,32,2),256>>>(4096,512,512, 512,512, a0,a1,a0,a0,
            nullptr,0, 1.f,nullptr, 1);
    }
    gemm_k<1,0><<<dim3(4,2,16),256>>>(256,512,4096, xq,256,0, ax,512,0, Tp,0,
        nullptr,invcol_q, 256, 1.f,nullptr, nullptr,nullptr,0,
        nullptr,nullptr,nullptr);
    splitk_reduceT<<<dim3(8,16,1),256>>>(16, 256, 512, Tp, Tt, Tt);
    {   GT a0 = {xq, invn2_q, Tt, nullptr, ux, out};
        gemm_t32<<<dim3(4,32,1),256>>>(4096,512,256, 256,256, a0,a0,a0,a0,
            nullptr,0, 1.f,nullptr, 0);
    }
}

// round 17
// speedup vs baseline: 1.0977x; 1.0136x over previous
#include <cuda_runtime.h>
#include <math.h>

#define NN 4096
#define C1 256
#define C2 512
#define CHW (256*4096)
#define CRP 256   // colred_part blocks

// ---------------- static scratch (no allocations allowed) ----------------
__device__ float g_xr[2*CHW];
__device__ float g_pos[CHW];
__device__ float g_bnsc[C1], g_bnsh[C1];
__device__ float g_partS[2*CRP*C2], g_partQ[2*CRP*C2];
__device__ float g_invn_s[C1], g_invn2_s[C1];
__device__ float g_invn_q[C1], g_invn2_q[C1];
__device__ float g_invn_e1[C2], g_dummy1[C2];
__device__ float g_invn_e2[C2], g_dummy2[C2];
__device__ float g_invee[C2];
__device__ float g_fsc[C2], g_fsh[C2];
__device__ float g_colabsPart[2*32*NN];
__device__ float g_invcol_s[NN], g_invcol_q[NN];
__device__ unsigned int g_rmax_ord;
__device__ float g_inv_rmax;
__device__ float g_ax[NN*C2];
__device__ float g_ux[NN*C2];
__device__ float g_ax2[NN*C2];
__device__ float g_ux2[NN*C2];
__device__ float g_Tt[C2*C2];
__device__ float g_Tt2[C2*C2];
__device__ float g_Tpart[16*C2*C2];
__device__ float g_emb1[NN*C2];
__device__ float g_emb2[NN*C2];
__device__ float g_r2[NN*C2];
__device__ float g_y2[NN*C2];

__device__ __forceinline__ unsigned ord_of_float(float f) {
    unsigned u = __float_as_uint(f);
    return (u & 0x80000000u) ? ~u : (u | 0x80000000u);
}
__device__ __forceinline__ unsigned f2tf32(float v) {
    unsigned r; asm("cvt.rna.tf32.f32 %0, %1;" : "=r"(r) : "f"(v)); return r;
}
__device__ __forceinline__ void mma_tf32(float* d, const unsigned* a, const unsigned* b) {
    asm volatile("mma.sync.aligned.m16n8k8.row.col.f32.tf32.tf32.f32 "
        "{%0,%1,%2,%3}, {%4,%5,%6,%7}, {%8,%9}, {%0,%1,%2,%3};"
        : "+f"(d[0]), "+f"(d[1]), "+f"(d[2]), "+f"(d[3])
        : "r"(a[0]), "r"(a[1]), "r"(a[2]), "r"(a[3]), "r"(b[0]), "r"(b[1]));
}

// per-z parameter set for the tf32 GEMM
struct GT {
    const float* A; const float* ksA; const float* B; int ldb;
    const float* bias; const float* addMat; const float* alphaPtr; float* C;
};

// ---------------- generic SGEMM 128x128x16, double-buffered smem ----------------
// splitLen>0: z in [0,16) slices of K on (A,B,ksB); z in [16,32) on (Ab,Bb,ksBb).
// Partials at C + z*M*N. splitLen==0: grid.z = batch with strides sA/sB/sC.
template<int TA, int TB>
__global__ void __launch_bounds__(256)
gemm_k(int M, int N, int K,
       const float* __restrict__ A, int lda, size_t sA,
       const float* __restrict__ B, int ldb, size_t sB,
       float* __restrict__ C, size_t sC,
       const float* __restrict__ ksA, const float* __restrict__ ksB,
       int splitLen, float alphaS, const float* __restrict__ alphaPtr,
       const float* __restrict__ bias,
       const float* __restrict__ addMat, int doRelu,
       const float* __restrict__ Ab, const float* __restrict__ Bb,
       const float* __restrict__ ksBb)
{
    __shared__ float As[2][16][128];
    __shared__ float Bs[2][16][128];
    const int tid = threadIdx.x;
    const int tx = tid & 15, ty = tid >> 4;
    const int n0 = blockIdx.x * 128;
    const int m0 = blockIdx.y * 128;
    const int z  = blockIdx.z;

    int k0, kEnd;
    if (splitLen > 0) {
        if (z >= 16) { A = Ab; B = Bb; ksB = ksBb; }
        k0 = (z & 15) * splitLen; kEnd = k0 + splitLen;
        C += (size_t)z * M * N;
    }
    else { k0 = 0; kEnd = K; A += (size_t)z*sA; B += (size_t)z*sB; C += (size_t)z*sC; }

    float acc[8][8];
    #pragma unroll
    for (int i=0;i<8;i++)
        #pragma unroll
        for (int j=0;j<8;j++) acc[i][j]=0.f;

    float4 rA0, rA1, rB0, rB1;

    auto loadA = [&](int kk, float4& a0, float4& a1) {
        if (TA == 0) {
            int m = tid >> 1, k8 = (tid & 1) * 8;
            const float* src = A + (size_t)(m0+m)*lda + kk + k8;
            a0 = *(const float4*)src; a1 = *(const float4*)(src+4);
        } else {
            int k = tid >> 4, m8 = (tid & 15) * 8;
            const float* src = A + (size_t)(kk+k)*lda + m0 + m8;
            a0 = *(const float4*)src; a1 = *(const float4*)(src+4);
        }
    };
    auto loadB = [&](int kk, float4& b0, float4& b1) {
        if (TB == 0) {
            int k = tid >> 4, n8 = (tid & 15) * 8;
            const float* src = B + (size_t)(kk+k)*ldb + n0 + n8;
            b0 = *(const float4*)src; b1 = *(const float4*)(src+4);
        } else {
            int n = tid >> 1, k8 = (tid & 1) * 8;
            const float* src = B + (size_t)(n0+n)*ldb + kk + k8;
            b0 = *(const float4*)src; b1 = *(const float4*)(src+4);
        }
    };
    auto storeA = [&](int buf, int kk, const float4& a0, const float4& a1) {
        float vv[8] = {a0.x,a0.y,a0.z,a0.w,a1.x,a1.y,a1.z,a1.w};
        if (TA == 0) {
            int m = tid >> 1, k8 = (tid & 1) * 8;
            #pragma unroll
            for (int i=0;i<8;i++) {
                float s = ksA ? ksA[kk+k8+i] : 1.f;
                As[buf][k8+i][m] = vv[i]*s;
            }
        } else {
            int k = tid >> 4, m8 = (tid & 15) * 8;
            float s = ksA ? ksA[kk+k] : 1.f;
            #pragma unroll
            for (int i=0;i<8;i++) As[buf][k][m8+i] = vv[i]*s;
        }
    };
    auto storeB = [&](int buf, int kk, const float4& b0, const float4& b1) {
        float vv[8] = {b0.x,b0.y,b0.z,b0.w,b1.x,b1.y,b1.z,b1.w};
        if (TB == 0) {
            int k = tid >> 4, n8 = (tid & 15) * 8;
            float s = ksB ? ksB[kk+k] : 1.f;
            #pragma unroll
            for (int i=0;i<8;i++) Bs[buf][k][n8+i] = vv[i]*s;
        } else {
            int n = tid >> 1, k8 = (tid & 1) * 8;
            #pragma unroll
            for (int i=0;i<8;i++) {
                float s = ksB ? ksB[kk+k8+i] : 1.f;
                Bs[buf][k8+i][n] = vv[i]*s;
            }
        }
    };

    loadA(k0, rA0, rA1); loadB(k0, rB0, rB1);
    storeA(0, k0, rA0, rA1); storeB(0, k0, rB0, rB1);
    __syncthreads();

    int buf = 0;
    for (int kk = k0; kk < kEnd; kk += 16) {
        const bool hasNext = (kk + 16) < kEnd;
        if (hasNext) { loadA(kk+16, rA0, rA1); loadB(kk+16, rB0, rB1); }
        #pragma unroll
        for (int k=0;k<16;k++) {
            float4 a0 = *(const float4*)&As[buf][k][ty*4];
            float4 a1 = *(const float4*)&As[buf][k][ty*4+64];
            float4 b0 = *(const float4*)&Bs[buf][k][tx*4];
            float4 b1 = *(const float4*)&Bs[buf][k][tx*4+64];
            float a[8] = {a0.x,a0.y,a0.z,a0.w,a1.x,a1.y,a1.z,a1.w};
            float b[8] = {b0.x,b0.y,b0.z,b0.w,b1.x,b1.y,b1.z,b1.w};
            #pragma unroll
            for (int i=0;i<8;i++)
                #pragma unroll
                for (int j=0;j<8;j++)
                    acc[i][j] += a[i]*b[j];
        }
        if (hasNext) {
            storeA(buf^1, kk+16, rA0, rA1);
            storeB(buf^1, kk+16, rB0, rB1);
            __syncthreads();
            buf ^= 1;
        }
    }

    if (splitLen > 0) {
        #pragma unroll
        for (int i=0;i<8;i++) {
            int m = m0 + ty*4 + (i&3) + ((i>>2)<<6);
            #pragma unroll
            for (int j=0;j<8;j++) {
                int n = n0 + tx*4 + (j&3) + ((j>>2)<<6);
                C[(size_t)m*N + n] = acc[i][j];
            }
        }
        return;
    }
    float alpha = alphaS * (alphaPtr ? *alphaPtr : 1.f);
    #pragma unroll
    for (int i=0;i<8;i++) {
        int m = m0 + ty*4 + (i&3) + ((i>>2)<<6);
        #pragma unroll
        for (int j=0;j<8;j++) {
            int n = n0 + tx*4 + (j&3) + ((j>>2)<<6);
            float v = acc[i][j]*alpha;
            if (bias)   v += bias[n];
            if (addMat) v += addMat[(size_t)m*N + n];
            if (doRelu) v = fmaxf(v, 0.f);
            C[(size_t)m*N + n] = v;
        }
    }
}

// --- tf32x3 tensor GEMM (PROVEN R13 body): C = act(alpha*(A*ksA)@B^T+bias+add)
// Block 128x128, 256 thr, 8 warps (2m x 4n), warp 64x32, k-tile 8, hi/lo smem.
// blockIdx.z selects one of 4 GT parameter sets (per-z B/ldb/bias/alphaPtr/C).
// A2/Ksplit: fused concat-K (z=0 path only).
__global__ void __launch_bounds__(256, 2)
gemm_t32(int M, int N, int K, int lda,
         GT g0, GT g1, GT g2, GT g3,
         const float* __restrict__ A2, int Ksplit, int doRelu)
{
    __shared__ unsigned sh[8192];
    const int tid = threadIdx.x, lane = tid & 31, wid = tid >> 5;
    const int wm = wid >> 2, wn = wid & 3;
    const int n0 = blockIdx.x * 128, m0 = blockIdx.y * 128;
    const int r = lane >> 2, c = lane & 3;
    const bool isA = tid < 128;
    const int row = isA ? tid : tid - 128;

    GT P = g0;
    if (blockIdx.z == 1) P = g1;
    else if (blockIdx.z == 2) P = g2;
    else if (blockIdx.z == 3) P = g3;

    float acc[4][4][4];
    #pragma unroll
    for (int mf=0; mf<4; mf++)
        #pragma unroll
        for (int nf=0; nf<4; nf++)
            #pragma unroll
            for (int q=0; q<4; q++) acc[mf][nf][q] = 0.f;

    float4 v0, v1;
    auto ldg = [&](int kk) {
        const float* p;
        if (isA) {
            const float* base = P.A; int kx = kk;
            if (A2 && kk >= Ksplit) { base = A2; kx = kk - Ksplit; }
            p = base + (size_t)(m0+row)*lda + kx;
        } else {
            p = P.B + (size_t)(n0+row)*P.ldb + kk;
        }
        v0 = *(const float4*)p; v1 = *(const float4*)(p+4);
    };
    auto sts = [&](int buf, int kk) {
        float a[8] = {v0.x,v0.y,v0.z,v0.w,v1.x,v1.y,v1.z,v1.w};
        if (isA && P.ksA) {
            #pragma unroll
            for (int i=0;i<8;i++) a[i] *= P.ksA[kk+i];
        }
        unsigned h[8], l[8];
        #pragma unroll
        for (int i=0;i<8;i++) {
            h[i] = f2tf32(a[i]);
            l[i] = f2tf32(a[i] - __uint_as_float(h[i]));
        }
        unsigned* hp = &sh[(isA ? 0 : 4096) + buf*1024 + row*8];
        unsigned* lp = hp + 2048;
        *(uint4*)hp     = make_uint4(h[0],h[4],h[1],h[5]);
        *(uint4*)(hp+4) = make_uint4(h[2],h[6],h[3],h[7]);
        *(uint4*)lp     = make_uint4(l[0],l[4],l[1],l[5]);
        *(uint4*)(lp+4) = make_uint4(l[2],l[6],l[3],l[7]);
    };

    ldg(0); sts(0, 0);
    __syncthreads();

    int buf = 0;
    for (int kk = 0; kk < K; kk += 8) {
        const bool nxt = (kk + 8) < K;
        if (nxt) ldg(kk + 8);
        const unsigned* Ah = &sh[buf*1024];
        const unsigned* Al = Ah + 2048;
        const unsigned* Bh = &sh[4096 + buf*1024];
        const unsigned* Bl = Bh + 2048;
        unsigned afh[4][4], afl[4][4], bfh[4][2], bfl[4][2];
        #pragma unroll
        for (int mf=0; mf<4; mf++) {
            int m = wm*64 + mf*16;
            uint2 p = *(const uint2*)&Ah[(m+r)*8 + 2*c];
            uint2 q = *(const uint2*)&Ah[(m+r+8)*8 + 2*c];
            afh[mf][0] = p.x; afh[mf][1] = q.x; afh[mf][2] = p.y; afh[mf][3] = q.y;
            uint2 pl = *(const uint2*)&Al[(m+r)*8 + 2*c];
            uint2 ql = *(const uint2*)&Al[(m+r+8)*8 + 2*c];
            afl[mf][0] = pl.x; afl[mf][1] = ql.x; afl[mf][2] = pl.y; afl[mf][3] = ql.y;
        }
        #pragma unroll
        for (int nf=0; nf<4; nf++) {
            uint2 p  = *(const uint2*)&Bh[(wn*32 + nf*8 + r)*8 + 2*c];
            bfh[nf][0] = p.x; bfh[nf][1] = p.y;
            uint2 pl = *(const uint2*)&Bl[(wn*32 + nf*8 + r)*8 + 2*c];
            bfl[nf][0] = pl.x; bfl[nf][1] = pl.y;
        }
        #pragma unroll
        for (int mf=0; mf<4; mf++)
            #pragma unroll
            for (int nf=0; nf<4; nf++) {
                mma_tf32(acc[mf][nf], afl[mf], bfh[nf]);
                mma_tf32(acc[mf][nf], afh[mf], bfl[nf]);
                mma_tf32(acc[mf][nf], afh[mf], bfh[nf]);
            }
        if (nxt) {
            sts(buf^1, kk + 8);
            __syncthreads();
            buf ^= 1;
        }
    }

    float alpha = P.alphaPtr ? *P.alphaPtr : 1.f;
    #pragma unroll
    for (int mf=0; mf<4; mf++) {
        #pragma unroll
        for (int h=0; h<2; h++) {
            int orow = m0 + wm*64 + mf*16 + r + h*8;
            #pragma unroll
            for (int nf=0; nf<4; nf++) {
                int col = n0 + wn*32 + nf*8 + 2*c;
                float w0 = acc[mf][nf][h*2]   * alpha;
                float w1 = acc[mf][nf][h*2+1] * alpha;
                if (P.bias)   { w0 += P.bias[col]; w1 += P.bias[col+1]; }
                if (P.addMat) { w0 += P.addMat[(size_t)orow*N + col];
                                w1 += P.addMat[(size_t)orow*N + col + 1]; }
                if (doRelu) { w0 = fmaxf(w0, 0.f); w1 = fmaxf(w1, 0.f); }
                *(float2*)&P.C[(size_t)orow*N + col] = make_float2(w0, w1);
            }
        }
    }
}

// ---- split-K reduce + transpose: out[n*M+m] = sum_z part[z][m][n], 32x32 tiles.
__global__ void splitk_reduceT(int S, int M, int N,
                               const float* __restrict__ part,
                               float* __restrict__ out0, float* __restrict__ out1)
{
    __shared__ float t[32][33];
    part += (size_t)blockIdx.z * S * M * N;
    float* out = blockIdx.z ? out1 : out0;
    int m0 = blockIdx.x*32, n0 = blockIdx.y*32;
    int g = threadIdx.x >> 5, ln = threadIdx.x & 31;
    #pragma unroll
    for (int i=0;i<4;i++) {
        int m = g*4 + i;
        float s = 0.f;
        #pragma unroll 4
        for (int z=0;z<16;z++)
            s += part[((size_t)z*M + m0+m)*N + n0+ln];
        t[m][ln] = s;
    }
    __syncthreads();
    #pragma unroll
    for (int i=0;i<4;i++) {
        int n = g*4 + i;
        out[(size_t)(n0+n)*M + m0 + ln] = t[ln][n];
    }
}

// ------------- streamed Gram stats via tf32 mma: G = (A*scA)(B*scB)^T ---------
__global__ void __launch_bounds__(256)
gram_tf32(int Cc,
          const float* __restrict__ A, int lda, const float* __restrict__ scA,
          const float* __restrict__ Bm, int ldb, const float* __restrict__ scB,
          const float* __restrict__ A1, const float* __restrict__ scA1,
          const float* __restrict__ B1, const float* __restrict__ scB1,
          float* __restrict__ colAbsPart, unsigned int* __restrict__ maxOrd)
{
    __shared__ unsigned sh[12288];   // exactly 48KB
    const int tid = threadIdx.x, lane = tid & 31, wid = tid >> 5;
    const int wm = wid >> 2, wn = wid & 3;
    const int m0 = blockIdx.x * 256;   // cols (Bm rows)
    const int n0 = blockIdx.y * 128;   // rows (A rows)
    const int r = lane >> 2, c = lane & 3;
    const int ar = tid >> 1, asl = tid & 1;

    if (blockIdx.z == 1) { A = A1; scA = scA1; Bm = B1; scB = scB1; }

    float acc[4][8][4];
    #pragma unroll
    for (int mf=0; mf<4; mf++)
        #pragma unroll
        for (int nf=0; nf<8; nf++)
            #pragma unroll
            for (int q=0; q<4; q++) acc[mf][nf][q] = 0.f;

    float4 vA0, vA1, vB0, vB1, vB2, vB3;
    auto ldg = [&](int cc) {
        const float* pa = A + (size_t)(n0+ar)*lda + cc + asl*8;
        vA0 = *(const float4*)pa; vA1 = *(const float4*)(pa+4);
        const float* pb = Bm + (size_t)(m0+tid)*ldb + cc;
        vB0 = *(const float4*)pb;     vB1 = *(const float4*)(pb+4);
        vB2 = *(const float4*)(pb+8); vB3 = *(const float4*)(pb+12);
    };
    auto sts = [&](int buf, int cc) {
        float a[8] = {vA0.x,vA0.y,vA0.z,vA0.w,vA1.x,vA1.y,vA1.z,vA1.w};
        #pragma unroll
        for (int i=0;i<8;i++) a[i] *= scA[cc + asl*8 + i];
        uint4 u0 = make_uint4(f2tf32(a[0]), f2tf32(a[4]), f2tf32(a[1]), f2tf32(a[5]));
        uint4 u1 = make_uint4(f2tf32(a[2]), f2tf32(a[6]), f2tf32(a[3]), f2tf32(a[7]));
        unsigned* ab = &sh[buf*2048 + asl*1024 + ar*8];
        *(uint4*)ab = u0; *(uint4*)(ab+4) = u1;
        float b[16] = {vB0.x,vB0.y,vB0.z,vB0.w, vB1.x,vB1.y,vB1.z,vB1.w,
                       vB2.x,vB2.y,vB2.z,vB2.w, vB3.x,vB3.y,vB3.z,vB3.w};
        #pragma unroll
        for (int i=0;i<16;i++) b[i] *= scB[cc + i];
        uint4 w0 = make_uint4(f2tf32(b[0]),  f2tf32(b[4]),  f2tf32(b[1]),  f2tf32(b[5]));
        uint4 w1 = make_uint4(f2tf32(b[2]),  f2tf32(b[6]),  f2tf32(b[3]),  f2tf32(b[7]));
        uint4 w2 = make_uint4(f2tf32(b[8]),  f2tf32(b[12]), f2tf32(b[9]),  f2tf32(b[13]));
        uint4 w3 = make_uint4(f2tf32(b[10]), f2tf32(b[14]), f2tf32(b[11]), f2tf32(b[15]));
        unsigned* bb = &sh[4096 + buf*4096 + tid*8];
        *(uint4*)bb = w0; *(uint4*)(bb+4) = w1;
        *(uint4*)(bb+2048) = w2; *(uint4*)(bb+2048+4) = w3;
    };

    ldg(0); sts(0, 0);
    __syncthreads();

    int buf = 0;
    for (int cc = 0; cc < Cc; cc += 16) {
        const bool nxt = (cc + 16) < Cc;
        if (nxt) ldg(cc + 16);
        #pragma unroll
        for (int s=0; s<2; s++) {
            const unsigned* Ab = &sh[buf*2048 + s*1024];
            const unsigned* Bb = &sh[4096 + buf*4096 + s*2048];
            unsigned af[4][4];
            #pragma unroll
            for (int mf=0; mf<4; mf++) {
                int m = wm*64 + mf*16;
                uint2 p = *(const uint2*)&Ab[(m+r)*8 + 2*c];
                uint2 q = *(const uint2*)&Ab[(m+r+8)*8 + 2*c];
                af[mf][0] = p.x; af[mf][1] = q.x; af[mf][2] = p.y; af[mf][3] = q.y;
            }
            unsigned bf[8][2];
            #pragma unroll
            for (int nf=0; nf<8; nf++) {
                uint2 p = *(const uint2*)&Bb[(wn*64 + nf*8 + r)*8 + 2*c];
                bf[nf][0] = p.x; bf[nf][1] = p.y;
            }
            #pragma unroll
            for (int mf=0; mf<4; mf++)
                #pragma unroll
                for (int nf=0; nf<8; nf++)
                    mma_tf32(acc[mf][nf], af[mf], bf[nf]);
        }
        if (nxt) {
            sts(buf^1, cc + 16);
            __syncthreads();
            buf ^= 1;
        }
    }
    float* cw  = (float*)&sh[4096];          // [8][64]
    float* wmx = (float*)&sh[4096 + 512];    // [8]

    if (colAbsPart) {
        #pragma unroll
        for (int nf=0; nf<8; nf++) {
            float s0 = 0.f, s1 = 0.f;
            #pragma unroll
            for (int mf=0; mf<4; mf++) {
                s0 += fabsf(acc[mf][nf][0]) + fabsf(acc[mf][nf][2]);
                s1 += fabsf(acc[mf][nf][1]) + fabsf(acc[mf][nf][3]);
            }
            #pragma unroll
            for (int off=4; off<32; off<<=1) {
                s0 += __shfl_xor_sync(0xffffffffu, s0, off);
                s1 += __shfl_xor_sync(0xffffffffu, s1, off);
            }
            if (lane < 4) {
                cw[wid*64 + nf*8 + 2*lane    ] = s0;
                cw[wid*64 + nf*8 + 2*lane + 1] = s1;
            }
        }
        __syncthreads();
        {
            int wn2 = tid >> 6, j = tid & 63;
            float s = cw[wn2*64 + j] + cw[(4+wn2)*64 + j];
            colAbsPart[(size_t)blockIdx.z*32*NN + (size_t)blockIdx.y*NN + m0 + tid] = s;
        }
    }
    if (maxOrd) {
        float mx = -3.4e38f;
        #pragma unroll
        for (int mf=0; mf<4; mf++)
            #pragma unroll
            for (int nf=0; nf<8; nf++)
                #pragma unroll
                for (int q=0; q<4; q++) mx = fmaxf(mx, acc[mf][nf][q]);
        #pragma unroll
        for (int off=16; off; off>>=1)
            mx = fmaxf(mx, __shfl_xor_sync(0xffffffffu, mx, off));
        if (lane == 0) wmx[wid] = mx;
        __syncthreads();
        if (tid == 0) {
            float m2 = wmx[0];
            #pragma unroll
            for (int t=1;t<8;t++) m2 = fmaxf(m2, wmx[t]);
            atomicMax(maxOrd, ord_of_float(m2));
        }
    }
}

// ---------------- small kernels ----------------
__global__ void convbn_stats(const float* __restrict__ xr, const float* __restrict__ g,
                             const float* __restrict__ b, float* sc, float* sh)
{
    int o = blockIdx.x;
    const float* p0 = xr + (size_t)o*4096;
    const float* p1 = xr + (size_t)CHW + (size_t)o*4096;
    float s=0.f, q=0.f;
    for (int i = threadIdx.x; i < 4096; i += 256) {
        float v = p0[i]; s += v; q += v*v;
        v = p1[i];       s += v; q += v*v;
    }
    __shared__ float ss[256], sq[256];
    ss[threadIdx.x]=s; sq[threadIdx.x]=q; __syncthreads();
    for (int off=128; off; off>>=1) {
        if (threadIdx.x < off) { ss[threadIdx.x]+=ss[threadIdx.x+off]; sq[threadIdx.x]+=sq[threadIdx.x+off]; }
        __syncthreads();
    }
    if (threadIdx.x == 0) {
        float mean = ss[0]/8192.f;
        float var  = sq[0]/8192.f - mean*mean;
        float scl  = g[o]*rsqrtf(var + 1e-5f);
        sc[o] = scl; sh[o] = b[o] - mean*scl;
    }
}

__global__ void bnrelu_k(float* x, const float* sc, const float* sh) {
    int i = blockIdx.x*256 + threadIdx.x;
    int o = (i >> 12) & 255;
    x[i] = fmaxf(x[i]*sc[o] + sh[o], 0.f);
}

__global__ void pos_kernel(const float* __restrict__ x0, const float* __restrict__ mask,
                           float* __restrict__ out)
{
    int gid = blockIdx.x*256 + threadIdx.x;
    int c = gid >> 12, p = gid & 4095;
    int i = p >> 6, j = p & 63;
    const float* img = x0 + (size_t)c*4096;
    float yd = i * (511.f/63.f);
    int Y0 = min((int)yd, 511), Y1 = min(Y0+1, 511);
    float wy = yd - (float)Y0;
    float xd = j * (511.f/63.f);
    int X0 = min((int)xd, 511), X1 = min(X0+1, 511);
    float wx = xd - (float)X0;
    int Ys[2]={Y0,Y1}; float wys[2]={1.f-wy, wy};
    int Xs[2]={X0,X1}; float wxs[2]={1.f-wx, wx};
    float acc = 0.f;
    #pragma unroll
    for (int a=0;a<2;a++) {
        int Y = Ys[a];
        float yu = Y*(63.f/511.f);
        int a0 = min((int)yu, 63), a1 = min(a0+1, 63);
        float wa = yu - (float)a0;
        #pragma unroll
        for (int b=0;b<2;b++) {
            int X = Xs[b];
            float xu = X*(63.f/511.f);
            int b0 = min((int)xu, 63), b1 = min(b0+1, 63);
            float wb = xu - (float)b0;
            float v = (img[a0*64+b0]*(1.f-wb) + img[a0*64+b1]*wb)*(1.f-wa)
                    + (img[a1*64+b0]*(1.f-wb) + img[a1*64+b1]*wb)*wa;
            acc += wys[a]*wxs[b]*mask[Y*512+X]*v;
        }
    }
    out[gid] = acc;
}

// z selects input X0/X1; addBoth: value = X0+X1 (use with gridDim.z==1).
__global__ void colred_part(const float* __restrict__ X0, const float* __restrict__ X1,
                            int ld, int C,
                            float* __restrict__ pS, float* __restrict__ pQ,
                            int addBoth)
{
    const float* X = blockIdx.z ? X1 : X0;
    size_t off = (size_t)blockIdx.z * CRP * C;
    int r0 = blockIdx.x * (NN/CRP);
    int c0 = threadIdx.x, c1 = threadIdx.x + 256;
    float s0=0,q0=0,s1=0,q1=0;
    #pragma unroll 4
    for (int r=0;r<NN/CRP;r++) {
        const float* row = X + (size_t)(r0+r)*ld;
        const float* rowB = X1 + (size_t)(r0+r)*ld;
        float v = row[c0]; if (addBoth) v += rowB[c0];
        s0 += v; q0 += v*v;
        if (C > 256) {
            float w = row[c1]; if (addBoth) w += rowB[c1];
            s1 += w; q1 += w*w;
        }
    }
    pS[off + blockIdx.x*C + c0] = s0; pQ[off + blockIdx.x*C + c0] = q0;
    if (C > 256) { pS[off + blockIdx.x*C + c1] = s1; pQ[off + blockIdx.x*C + c1] = q1; }
}

// mode 0: o1=1/max(||col||,eps), o2=o1^2.  mode 1: BN scale/shift over 4096 rows.
// z==1 switches to o1b/o2b and partial slice 1.
__global__ void colred_fin(const float* __restrict__ pS, const float* __restrict__ pQ,
                           int C, int mode,
                           const float* g, const float* b,
                           float* o1, float* o2, float* o1b, float* o2b)
{
    if (blockIdx.z == 1) { o1 = o1b; o2 = o2b; }
    size_t off = (size_t)blockIdx.z * CRP * C;
    int c = blockIdx.x*256 + threadIdx.x;
    if (c >= C) return;
    float S=0.f, Q=0.f;
    #pragma unroll 4
    for (int z=0; z<CRP; z++) { S += pS[off + z*C+c]; Q += pQ[off + z*C+c]; }
    if (mode == 0) {
        float inv = 1.f / fmaxf(sqrtf(Q), 1e-12f);
        o1[c] = inv; o2[c] = inv*inv;
    } else {
        float mean = S*(1.f/4096.f);
        float var  = Q*(1.f/4096.f) - mean*mean;
        float sc   = g[c]*rsqrtf(var + 1e-5f);
        o1[c] = sc; o2[c] = b[c] - mean*sc;
    }
}

__global__ void colabs_fin(const float* __restrict__ part,
                           float* __restrict__ inv0, float* __restrict__ inv1)
{
    const float* p = part + (size_t)blockIdx.z*32*NN;
    float* inv = blockIdx.z ? inv1 : inv0;
    int m = blockIdx.x*256 + threadIdx.x;
    float s = 0.f;
    #pragma unroll 4
    for (int z=0; z<32; z++) s += p[z*NN + m];
    inv[m] = 1.f / fmaxf(s, 1e-12f);
}

__global__ void vecmul_k(const float* a, const float* b, float* o) {
    int i = blockIdx.x*256 + threadIdx.x;
    o[i] = a[i]*b[i];
}

__global__ void init_rmax_k(unsigned int* p) { *p = 0u; }
__global__ void fin_rmax_k(const unsigned int* p, float* o) {
    unsigned u = *p;
    unsigned f = (u & 0x80000000u) ? (u & 0x7fffffffu) : ~u;
    *o = 1.f / __uint_as_float(f);
}

// o = relu((y0+y1)*sc + sh)
__global__ void bnapply_k(const float* y0, const float* y1,
                          const float* sc, const float* sh, float* o) {
    int i = blockIdx.x*256 + threadIdx.x;
    int c = i & 511;
    o[i] = fmaxf((y0[i]+y1[i])*sc[c] + sh[c], 0.f);
}

// ---------------- host ----------------
#define SYMF(name, sym) float* name; { void* _p=nullptr; cudaGetSymbolAddress(&_p, sym); name=(float*)_p; }

extern "C" void kernel_launch(void* const* d_in, const int* in_sizes, int n_in,
                              void* d_out, int out_size)
{
    const float* x      = (const float*)d_in[0];
    const float* mask   = (const float*)d_in[1];
    const float* conv1w = (const float*)d_in[2];
    const float* bn1g   = (const float*)d_in[3];
    const float* bn1b   = (const float*)d_in[4];
    const float* g0aw   = (const float*)d_in[5];
    const float* g0ab   = (const float*)d_in[6];
    const float* g0uw   = (const float*)d_in[7];
    const float* g0ub   = (const float*)d_in[8];
    const float* g1aw   = (const float*)d_in[9];
    const float* g1ab   = (const float*)d_in[10];
    const float* g1uw   = (const float*)d_in[11];
    const float* g1ub   = (const float*)d_in[12];
    const float* cgw    = (const float*)d_in[13];
    const float* cgb    = (const float*)d_in[14];
    const float* cgbng  = (const float*)d_in[15];
    const float* cgbnb  = (const float*)d_in[16];
    float* out = (float*)d_out;

    SYMF(xr, g_xr)       SYMF(pos, g_pos)
    SYMF(bnsc, g_bnsc)   SYMF(bnsh, g_bnsh)
    SYMF(pS, g_partS)    SYMF(pQ, g_partQ)
    SYMF(invn_s, g_invn_s)   SYMF(invn2_s, g_invn2_s)
    SYMF(invn_q, g_invn_q)   SYMF(invn2_q, g_invn2_q)
    SYMF(invn_e1, g_invn_e1) SYMF(dum1, g_dummy1)
    SYMF(invn_e2, g_invn_e2) SYMF(dum2, g_dummy2)
    SYMF(invee, g_invee)
    SYMF(fsc, g_fsc)     SYMF(fsh, g_fsh)
    SYMF(cap, g_colabsPart)
    SYMF(invcol_s, g_invcol_s) SYMF(invcol_q, g_invcol_q)
    SYMF(ax, g_ax)       SYMF(ux, g_ux)
    SYMF(ax2, g_ax2)     SYMF(ux2, g_ux2)
    SYMF(Tt, g_Tt)       SYMF(Tt2, g_Tt2)  SYMF(Tp, g_Tpart)
    SYMF(e1, g_emb1)     SYMF(e2, g_emb2)
    SYMF(y2b, g_r2)      SYMF(y2, g_y2)
    SYMF(invr, g_inv_rmax)
    unsigned int* rmo; { void* _p=nullptr; cudaGetSymbolAddress(&_p, g_rmax_ord); rmo=(unsigned int*)_p; }

    const float* xq = xr + CHW;

    // conv1 (fp32) -> BN -> relu -> pos
    gemm_k<0,0><<<dim3(32,2,2),256>>>(256,4096,512, conv1w,512,0, x,4096,(size_t)512*4096,
        xr,(size_t)CHW, nullptr,nullptr, 0, 1.f,nullptr, nullptr,nullptr,0,
        nullptr,nullptr,nullptr);
    convbn_stats<<<256,256>>>(xr, bn1g, bn1b, bnsc, bnsh);
    bnrelu_k<<<2*CHW/256,256>>>(xr, bnsc, bnsh);
    pos_kernel<<<CHW/256,256>>>(xr, mask, pos);

    // ---- layer 0, BOTH graphs batched over z ----
    {   GT a0 = {xq,  nullptr, g0aw, 256, g0ab, nullptr, nullptr, ax };
        GT a1 = {xq,  nullptr, g0uw, 256, g0ub, nullptr, nullptr, ux };
        GT a2 = {pos, nullptr, g0aw, 256, g0ab, nullptr, nullptr, ax2};
        GT a3 = {pos, nullptr, g0uw, 256, g0ub, nullptr, nullptr, ux2};
        gemm_t32<<<dim3(4,32,4),256>>>(4096,512,256, 256, a0,a1,a2,a3,
            nullptr,0, 1);
    }
    colred_part<<<dim3(CRP,1,2),256>>>(xq, pos, 256, 256, pS, pQ, 0);
    colred_fin<<<dim3(1,1,2),256>>>(pS, pQ, 256, 0, nullptr,nullptr,
        invn_q, invn2_q, invn_s, invn2_s);
    gram_tf32<<<dim3(16,32,2),256>>>(256, xq,256,invn_q, xq,256,invn_q,
        pos, invn_s, pos, invn_s, cap, nullptr);
    colabs_fin<<<dim3(16,1,2),256>>>(cap, invcol_q, invcol_s);
    gemm_k<1,0><<<dim3(4,2,32),256>>>(256,512,4096, xq,256,0, ax,512,0, Tp,0,
        nullptr,invcol_q, 256, 1.f,nullptr, nullptr,nullptr,0,
        pos, ax2, invcol_s);
    splitk_reduceT<<<dim3(8,16,2),256>>>(16, 256, 512, Tp, Tt, Tt2);
    {   GT a0 = {xq,  invn2_q, Tt,  256, nullptr, ux,  nullptr, e2};
        GT a1 = {pos, invn2_s, Tt2, 256, nullptr, ux2, nullptr, e1};
        gemm_t32<<<dim3(4,32,2),256>>>(4096,512,256, 256, a0,a1,a0,a0,
            nullptr,0, 0);
    }

    // ---- R = adjacency(emb1, emb2) ----
    colred_part<<<dim3(CRP,1,2),256>>>(e1, e2, 512, 512, pS, pQ, 0);
    colred_fin<<<dim3(2,1,2),256>>>(pS, pQ, 512, 0, nullptr,nullptr,
        invn_e1, dum1, invn_e2, dum2);
    vecmul_k<<<2,256>>>(invn_e1, invn_e2, invee);
    init_rmax_k<<<1,1>>>(rmo);
    gram_tf32<<<dim3(16,32,1),256>>>(512, e1,512,invn_e1, e2,512,invn_e2,
        nullptr,nullptr,nullptr,nullptr, nullptr, rmo);
    fin_rmax_k<<<1,1>>>(rmo, invr);

    // ---- cross for emb2 (restructured): T = e1^T e1 (symmetric) ----
    gemm_k<1,0><<<dim3(4,4,16),256>>>(512,512,4096, e1,512,0, e1,512,0, Tp,0,
        nullptr,nullptr, 256, 1.f,nullptr, nullptr,nullptr,0,
        nullptr,nullptr,nullptr);
    splitk_reduceT<<<dim3(16,16,1),256>>>(16, 512, 512, Tp, Tt, Tt);
    // T3 = Wr @ T  (Wr = cgw[:,512:]); reuse Tt2 as T3 (free here)
    {   GT a0 = {cgw+512, nullptr, Tt, 512, nullptr, nullptr, nullptr, Tt2};
        gemm_t32<<<dim3(4,4,1),256>>>(512,512,512, 1024, a0,a0,a0,a0,
            nullptr,0, 0);
    }
    // y2 = e2@Wl^T + cgb ; y2b = invr*(e2*invee)@T3^T  — batched z=2
    {   GT a0 = {e2, nullptr, cgw, 1024, cgb,     nullptr, nullptr, y2 };
        GT a1 = {e2, invee,   Tt2, 512,  nullptr, nullptr, invr,    y2b};
        gemm_t32<<<dim3(4,32,2),256>>>(4096,512,512, 512, a0,a1,a0,a0,
            nullptr,0, 0);
    }
    colred_part<<<dim3(CRP,1,1),256>>>(y2, y2b, 512, 512, pS, pQ, 1);
    colred_fin<<<dim3(2,1,1),256>>>(pS, pQ, 512, 1, cgbng, cgbnb,
        fsc, fsh, nullptr, nullptr);
    bnapply_k<<<NN*512/256,256>>>(y2, y2b, fsc, fsh, e2);

    // ---- layer 1 for emb2 ----
    {   GT a0 = {e2, nullptr, g1aw, 512, g1ab, nullptr, nullptr, ax};
        GT a1 = {e2, nullptr, g1uw, 512, g1ub, nullptr, nullptr, ux};
        gemm_t32<<<dim3(4,32,2),256>>>(4096,512,512, 512, a0,a1,a0,a0,
            nullptr,0, 1);
    }
    gemm_k<1,0><<<dim3(4,2,16),256>>>(256,512,4096, xq,256,0, ax,512,0, Tp,0,
        nullptr,invcol_q, 256, 1.f,nullptr, nullptr,nullptr,0,
        nullptr,nullptr,nullptr);
    splitk_reduceT<<<dim3(8,16,1),256>>>(16, 256, 512, Tp, Tt, Tt);
    {   GT a0 = {xq, invn2_q, Tt, 256, nullptr, ux, nullptr, out};
        gemm_t32<<<dim3(4,32,1),256>>>(4096,512,256, 256, a0,a0,a0,a0,
            nullptr,0, 0);
    }
}